// round 1
// baseline (speedup 1.0000x reference)
#include <cuda_runtime.h>
#include <math.h>

#define Bb 128
#define Tt 30
#define Vv 10000
#define Ee 512
#define Hh 512
#define Ff 4096
#define BH (Bb*Hh)          // 65536
#define TBH (Tt*Bb*Hh)      // 1966080
#define SPLITK 16

// ---------------- scratch (device globals; no allocation) ----------------
__device__ float g_h0[BH];
__device__ float g_h1[BH];
__device__ float g_u0[BH];
__device__ float g_rh0[BH];
__device__ float g_u1[BH];
__device__ float g_conc1[Bb*2*Hh];   // [h0', h1]
__device__ float g_conc2[Bb*2*Hh];   // [h0', r1*h1]
__device__ float g_xemb[TBH];        // [T*B, E], row = t*B+b
__device__ float g_Xu0[TBH];
__device__ float g_Xr0[TBH];
__device__ float g_Xc0[TBH];
__device__ float g_X1[TBH];          // top-layer h per step, row = t*B+b
__device__ float g_part[SPLITK*BH];  // split-K partials for init GEMM

__device__ __forceinline__ float sigmoidf_(float x) { return 1.0f / (1.0f + expf(-x)); }

// ---------------- 64x64x16 fp32 tiled GEMM core ----------------
// A [*,lda] row-major, B [*,ldb] row-major. Computes tile (m0,n0), K range [kBeg,kEnd).
// 256 threads, each thread 4x4. M must be multiple of 64; N guarded.
__device__ __forceinline__ void gemm64_core(
    const float* __restrict__ A, int lda,
    const float* __restrict__ Bw, int ldb, int N,
    int kBeg, int kEnd, int m0, int n0,
    float (&acc)[4][4], float (*As)[64], float (*Bs)[64])
{
    const int tid  = threadIdx.x;
    const int arow = tid >> 2;          // 0..63
    const int ak4  = (tid & 3) * 4;     // 0,4,8,12
    const int brow = tid >> 4;          // 0..15
    const int bn4  = (tid & 15) * 4;    // 0..60
    const int ty   = tid >> 4, tx = tid & 15;

    for (int k0 = kBeg; k0 < kEnd; k0 += 16) {
        float4 a4 = *reinterpret_cast<const float4*>(&A[(m0 + arow) * lda + k0 + ak4]);
        As[ak4 + 0][arow] = a4.x;
        As[ak4 + 1][arow] = a4.y;
        As[ak4 + 2][arow] = a4.z;
        As[ak4 + 3][arow] = a4.w;

        int ncol = n0 + bn4;
        float4 b4 = make_float4(0.f, 0.f, 0.f, 0.f);
        if (ncol < N)
            b4 = *reinterpret_cast<const float4*>(&Bw[(k0 + brow) * ldb + ncol]);
        *reinterpret_cast<float4*>(&Bs[brow][bn4]) = b4;

        __syncthreads();
        #pragma unroll
        for (int kk = 0; kk < 16; kk++) {
            float4 av = *reinterpret_cast<const float4*>(&As[kk][ty * 4]);
            float4 bv = *reinterpret_cast<const float4*>(&Bs[kk][tx * 4]);
            float a[4] = {av.x, av.y, av.z, av.w};
            float b[4] = {bv.x, bv.y, bv.z, bv.w};
            #pragma unroll
            for (int i = 0; i < 4; i++)
                #pragma unroll
                for (int j = 0; j < 4; j++)
                    acc[i][j] = fmaf(a[i], b[j], acc[i][j]);
        }
        __syncthreads();
    }
}

#define GEMM_PROLOGUE() \
    __shared__ float As[16][64]; \
    __shared__ float Bs[16][64]; \
    float acc[4][4] = {}; \
    const int m0 = blockIdx.y * 64, n0 = blockIdx.x * 64; \
    const int ty = threadIdx.x >> 4, tx = threadIdx.x & 15;

// ---------------- init: h0 = tanh(vgg @ W_in + b_in), split-K ----------------
__global__ __launch_bounds__(256) void k_init_part(const float* __restrict__ A,
                                                   const float* __restrict__ W)
{
    GEMM_PROLOGUE();
    int kb = blockIdx.z * (Ff / SPLITK);
    gemm64_core(A, Ff, W, Hh, Hh, kb, kb + Ff / SPLITK, m0, n0, acc, As, Bs);
    #pragma unroll
    for (int i = 0; i < 4; i++)
        #pragma unroll
        for (int j = 0; j < 4; j++) {
            int r = m0 + ty * 4 + i, c = n0 + tx * 4 + j;
            g_part[blockIdx.z * BH + r * Hh + c] = acc[i][j];
        }
}

__global__ __launch_bounds__(256) void k_init_reduce(const float* __restrict__ b_in)
{
    int i = blockIdx.x * 256 + threadIdx.x;   // 0..BH-1
    float s = 0.f;
    #pragma unroll
    for (int z = 0; z < SPLITK; z++) s += g_part[z * BH + i];
    float v = tanhf(s + b_in[i & (Hh - 1)]);
    g_h0[i] = v;
    g_h1[i] = v;
    int b = i >> 9, n = i & (Hh - 1);
    g_conc1[b * (2 * Hh) + Hh + n] = v;       // second half = h1
}

// ---------------- gather embedding into [T*B, E] (row = t*B+b) ----------------
__global__ __launch_bounds__(256) void k_gather(const float* __restrict__ emb,
                                                const int* __restrict__ tok)
{
    int idx = blockIdx.x * 256 + threadIdx.x;   // over T*B*(E/4)
    int r   = idx >> 7;                          // E/4 = 128
    int e4  = (idx & 127) * 4;
    int t   = r >> 7;                            // B = 128
    int b   = r & 127;
    int token = tok[b * Tt + t];
    float4 v = *reinterpret_cast<const float4*>(&emb[token * Ee + e4]);
    *reinterpret_cast<float4*>(&g_xemb[r * Ee + e4]) = v;
}

// ---------------- layer0 x-projections for all timesteps ----------------
__global__ __launch_bounds__(256) void k_xpre(const float* __restrict__ Wu0x,
                                              const float* __restrict__ Wr0x,
                                              const float* __restrict__ Wc0x,
                                              const float* __restrict__ bu0,
                                              const float* __restrict__ br0,
                                              const float* __restrict__ bc0)
{
    GEMM_PROLOGUE();
    int z = blockIdx.z;
    const float* W  = (z == 0) ? Wu0x : (z == 1) ? Wr0x : Wc0x;
    const float* bi = (z == 0) ? bu0  : (z == 1) ? br0  : bc0;
    float* out      = (z == 0) ? g_Xu0 : (z == 1) ? g_Xr0 : g_Xc0;
    gemm64_core(g_xemb, Ee, W, Hh, Hh, 0, Ee, m0, n0, acc, As, Bs);
    #pragma unroll
    for (int i = 0; i < 4; i++)
        #pragma unroll
        for (int j = 0; j < 4; j++) {
            int r = m0 + ty * 4 + i, c = n0 + tx * 4 + j;
            out[r * Hh + c] = acc[i][j] + bi[c];
        }
}

// ---------------- step: layer0 u,r gates ----------------
__global__ __launch_bounds__(256) void k_step_ur0(int t,
                                                  const float* __restrict__ Wu0h,
                                                  const float* __restrict__ Wr0h)
{
    GEMM_PROLOGUE();
    int z = blockIdx.z;
    const float* W = z ? Wr0h : Wu0h;
    const float* X = (z ? g_Xr0 : g_Xu0) + t * BH;
    gemm64_core(g_h0, Hh, W, Hh, Hh, 0, Hh, m0, n0, acc, As, Bs);
    #pragma unroll
    for (int i = 0; i < 4; i++)
        #pragma unroll
        for (int j = 0; j < 4; j++) {
            int r = m0 + ty * 4 + i, c = n0 + tx * 4 + j;
            int idx = r * Hh + c;
            float s = sigmoidf_(acc[i][j] + X[idx]);
            if (z == 0) g_u0[idx] = s;
            else        g_rh0[idx] = s * g_h0[idx];
        }
}

// ---------------- step: layer0 candidate + GRU update ----------------
__global__ __launch_bounds__(256) void k_step_c0(int t, const float* __restrict__ Wc0h)
{
    GEMM_PROLOGUE();
    gemm64_core(g_rh0, Hh, Wc0h, Hh, Hh, 0, Hh, m0, n0, acc, As, Bs);
    const float* Xc = g_Xc0 + t * BH;
    #pragma unroll
    for (int i = 0; i < 4; i++)
        #pragma unroll
        for (int j = 0; j < 4; j++) {
            int r = m0 + ty * 4 + i, c = n0 + tx * 4 + j;
            int idx = r * Hh + c;
            float cand = tanhf(acc[i][j] + Xc[idx]);
            float u = g_u0[idx], h = g_h0[idx];
            float hn = u * h + (1.0f - u) * cand;
            g_h0[idx] = hn;
            g_conc1[r * (2 * Hh) + c] = hn;
            g_conc2[r * (2 * Hh) + c] = hn;
        }
}

// ---------------- step: layer1 u,r gates (K = 2H) ----------------
__global__ __launch_bounds__(256) void k_step_ur1(const float* __restrict__ Wu1,
                                                  const float* __restrict__ Wr1,
                                                  const float* __restrict__ bu1,
                                                  const float* __restrict__ br1)
{
    GEMM_PROLOGUE();
    int z = blockIdx.z;
    const float* W  = z ? Wr1 : Wu1;
    const float* bi = z ? br1 : bu1;
    gemm64_core(g_conc1, 2 * Hh, W, Hh, Hh, 0, 2 * Hh, m0, n0, acc, As, Bs);
    #pragma unroll
    for (int i = 0; i < 4; i++)
        #pragma unroll
        for (int j = 0; j < 4; j++) {
            int r = m0 + ty * 4 + i, c = n0 + tx * 4 + j;
            int idx = r * Hh + c;
            float s = sigmoidf_(acc[i][j] + bi[c]);
            if (z == 0) g_u1[idx] = s;
            else        g_conc2[r * (2 * Hh) + Hh + c] = s * g_h1[idx];
        }
}

// ---------------- step: layer1 candidate + GRU update (K = 2H) ----------------
__global__ __launch_bounds__(256) void k_step_c1(int t,
                                                 const float* __restrict__ Wc1,
                                                 const float* __restrict__ bc1)
{
    GEMM_PROLOGUE();
    gemm64_core(g_conc2, 2 * Hh, Wc1, Hh, Hh, 0, 2 * Hh, m0, n0, acc, As, Bs);
    #pragma unroll
    for (int i = 0; i < 4; i++)
        #pragma unroll
        for (int j = 0; j < 4; j++) {
            int r = m0 + ty * 4 + i, c = n0 + tx * 4 + j;
            int idx = r * Hh + c;
            float cand = tanhf(acc[i][j] + bc1[c]);
            float u = g_u1[idx], h = g_h1[idx];
            float hn = u * h + (1.0f - u) * cand;
            g_h1[idx] = hn;
            g_conc1[r * (2 * Hh) + Hh + c] = hn;
            g_X1[t * BH + idx] = hn;
        }
}

// ---------------- deferred logits: [T*B, H] @ [H, V] ----------------
__global__ __launch_bounds__(256) void k_logits(const float* __restrict__ Wout,
                                                const float* __restrict__ bout,
                                                float* __restrict__ out)
{
    GEMM_PROLOGUE();
    gemm64_core(g_X1, Hh, Wout, Vv, Vv, 0, Hh, m0, n0, acc, As, Bs);
    #pragma unroll
    for (int i = 0; i < 4; i++)
        #pragma unroll
        for (int j = 0; j < 4; j++) {
            int r = m0 + ty * 4 + i, c = n0 + tx * 4 + j;
            if (c < Vv) {
                int t = r >> 7, b = r & 127;   // r = t*B+b
                out[((long long)(b * Tt + t)) * Vv + c] = acc[i][j] + bout[c];
            }
        }
}

// ---------------- final states into output tail ----------------
__global__ __launch_bounds__(256) void k_final(float* __restrict__ out)
{
    int i = blockIdx.x * 256 + threadIdx.x;   // 0 .. 2*BH-1
    int l = i >> 16;                           // BH = 65536
    int j = i & (BH - 1);
    out[(long long)Bb * Tt * Vv + i] = l ? g_h1[j] : g_h0[j];
}

// ---------------- launch ----------------
extern "C" void kernel_launch(void* const* d_in, const int* in_sizes, int n_in,
                              void* d_out, int out_size)
{
    const float* vgg   = (const float*)d_in[0];
    const int*   xTok  = (const int*)  d_in[1];
    const float* emb   = (const float*)d_in[2];
    const float* W_in  = (const float*)d_in[3];
    const float* b_in  = (const float*)d_in[4];
    const float* Wu    = (const float*)d_in[5];
    const float* bu    = (const float*)d_in[6];
    const float* Wr    = (const float*)d_in[7];
    const float* br    = (const float*)d_in[8];
    const float* Wc    = (const float*)d_in[9];
    const float* bc    = (const float*)d_in[10];
    const float* W_out = (const float*)d_in[11];
    const float* b_out = (const float*)d_in[12];
    float* out = (float*)d_out;

    // weight slices: W*[l] is [(E+H), H] row-major; x-part rows [0,E), h-part [E,E+H)
    const float* Wu0x = Wu;                const float* Wu0h = Wu + Ee * Hh;
    const float* Wr0x = Wr;                const float* Wr0h = Wr + Ee * Hh;
    const float* Wc0x = Wc;                const float* Wc0h = Wc + Ee * Hh;
    const float* Wu1  = Wu + (Ee + Hh) * Hh;
    const float* Wr1  = Wr + (Ee + Hh) * Hh;
    const float* Wc1  = Wc + (Ee + Hh) * Hh;
    const float* bu1  = bu + Hh;
    const float* br1  = br + Hh;
    const float* bc1  = bc + Hh;

    // init hidden state (split-K GEMM + reduce)
    k_init_part<<<dim3(Hh / 64, Bb / 64, SPLITK), 256>>>(vgg, W_in);
    k_init_reduce<<<BH / 256, 256>>>(b_in);

    // gather embeddings + precompute layer0 x-projections (incl. biases)
    k_gather<<<(Tt * Bb * (Ee / 4)) / 256, 256>>>(emb, xTok);
    k_xpre<<<dim3(Hh / 64, (Tt * Bb) / 64, 3), 256>>>(Wu0x, Wr0x, Wc0x, bu, br, bc);

    // sequential GRU scan
    for (int t = 0; t < Tt; t++) {
        k_step_ur0<<<dim3(Hh / 64, Bb / 64, 2), 256>>>(t, Wu0h, Wr0h);
        k_step_c0 <<<dim3(Hh / 64, Bb / 64),    256>>>(t, Wc0h);
        k_step_ur1<<<dim3(Hh / 64, Bb / 64, 2), 256>>>(Wu1, Wr1, bu1, br1);
        k_step_c1 <<<dim3(Hh / 64, Bb / 64),    256>>>(t, Wc1, bc1);
    }

    // deferred big logits GEMM + final states
    k_logits<<<dim3((Vv + 63) / 64, (Tt * Bb) / 64), 256>>>(W_out, b_out, out);
    k_final<<<(2 * BH) / 256, 256>>>(out);
}

// round 2
// speedup vs baseline: 1.1937x; 1.1937x over previous
#include <cuda_runtime.h>
#include <math.h>

#define Bb 128
#define Tt 30
#define Vv 10000
#define Ee 512
#define Hh 512
#define Ff 4096
#define BH (Bb*Hh)          // 65536
#define TBH (Tt*Bb*Hh)      // 1966080
#define SPLITK 16

typedef unsigned long long u64;

// ---------------- scratch (device globals; no allocation) ----------------
__device__ float g_h0[BH];
__device__ float g_h1[BH];
__device__ float g_u0[BH];
__device__ float g_rh0[BH];
__device__ float g_u1[BH];
__device__ float g_conc1[Bb*2*Hh];      // [h0(w-1), h1(w-2)] for ur layer1
__device__ float g_conc2[2][Bb*2*Hh];   // double-buffered [h0(t1), r1*h1(t1-1)]
__device__ float g_xemb[TBH];
__device__ float g_Xu0[TBH];
__device__ float g_Xr0[TBH];
__device__ float g_Xc0[TBH];
__device__ float g_X1[TBH];             // top-layer h per step, row = t*B+b
__device__ float g_part[SPLITK*BH];

__device__ __forceinline__ float sigmoidf_(float x) { return 1.0f / (1.0f + expf(-x)); }
__device__ __forceinline__ u64 dup2(float x)  { float2 f = make_float2(x, x); return *reinterpret_cast<u64*>(&f); }
__device__ __forceinline__ u64 pack2(float x, float y) { float2 f = make_float2(x, y); return *reinterpret_cast<u64*>(&f); }
__device__ __forceinline__ void fma2(u64& d, u64 a, u64 b) {
    asm("fma.rn.f32x2 %0, %1, %2, %0;" : "+l"(d) : "l"(a), "l"(b));
}
__device__ __forceinline__ float2 unpk(u64 v) { return *reinterpret_cast<float2*>(&v); }

// ---------------- packed-f32x2 tiled GEMM core ----------------
// 256 threads as 16x16 (ty,tx). Tile TM x TN, K-tile 16. Per-thread RM=TM/16 rows,
// CP=TN/32 column-pairs. A pre-duplicated {a,a} in smem; B packed pairs.
template<int TM, int TN>
struct SmemT {
    u64 As2[16][TM + 1];
    u64 Bs2[16][TN/2 + 1];
};

template<int TM, int TN>
__device__ __forceinline__ void gemm_core2(
    const float* __restrict__ A, int lda,
    const float* __restrict__ Bw, int ldb, int N,
    int kBeg, int kEnd, int m0, int n0,
    u64 (&acc)[TM/16][TN/32], SmemT<TM,TN>& s)
{
    const int tid = threadIdx.x;
    const int ty = tid >> 4, tx = tid & 15;
    constexpr int RM = TM/16, CP = TN/32;

    for (int k0 = kBeg; k0 < kEnd; k0 += 16) {
        // load A tile [TM x 16] -> As2 (duplicated pairs)
        for (int v = tid; v < TM*4; v += 256) {
            int row = v >> 2, kq = (v & 3) << 2;
            float4 a = *reinterpret_cast<const float4*>(&A[(m0 + row) * lda + k0 + kq]);
            s.As2[kq + 0][row] = dup2(a.x);
            s.As2[kq + 1][row] = dup2(a.y);
            s.As2[kq + 2][row] = dup2(a.z);
            s.As2[kq + 3][row] = dup2(a.w);
        }
        // load B tile [16 x TN] -> Bs2 (packed col pairs), N-guarded
        for (int v = tid; v < TN*4; v += 256) {
            int row = v / (TN/4), cq = v % (TN/4);
            int ncol = n0 + cq * 4;
            float4 b;
            if (ncol + 3 < N) {
                b = *reinterpret_cast<const float4*>(&Bw[(k0 + row) * ldb + ncol]);
            } else {
                b.x = (ncol + 0 < N) ? Bw[(k0 + row) * ldb + ncol + 0] : 0.f;
                b.y = (ncol + 1 < N) ? Bw[(k0 + row) * ldb + ncol + 1] : 0.f;
                b.z = (ncol + 2 < N) ? Bw[(k0 + row) * ldb + ncol + 2] : 0.f;
                b.w = (ncol + 3 < N) ? Bw[(k0 + row) * ldb + ncol + 3] : 0.f;
            }
            s.Bs2[row][cq*2 + 0] = pack2(b.x, b.y);
            s.Bs2[row][cq*2 + 1] = pack2(b.z, b.w);
        }
        __syncthreads();
        #pragma unroll
        for (int kk = 0; kk < 16; kk++) {
            u64 av[RM], bv[CP];
            #pragma unroll
            for (int i = 0; i < RM; i++) av[i] = s.As2[kk][ty*RM + i];
            #pragma unroll
            for (int j = 0; j < CP; j++) bv[j] = s.Bs2[kk][tx*CP + j];
            #pragma unroll
            for (int i = 0; i < RM; i++)
                #pragma unroll
                for (int j = 0; j < CP; j++)
                    fma2(acc[i][j], av[i], bv[j]);
        }
        __syncthreads();
    }
}

// ---------------- init: h0 = tanh(vgg @ W_in + b_in), split-K ----------------
__global__ __launch_bounds__(256) void k_init_part(const float* __restrict__ A,
                                                   const float* __restrict__ W)
{
    __shared__ SmemT<64,64> s;
    u64 acc[4][2] = {};
    const int m0 = blockIdx.y * 64, n0 = blockIdx.x * 64;
    const int ty = threadIdx.x >> 4, tx = threadIdx.x & 15;
    int kb = blockIdx.z * (Ff / SPLITK);
    gemm_core2<64,64>(A, Ff, W, Hh, Hh, kb, kb + Ff/SPLITK, m0, n0, acc, s);
    #pragma unroll
    for (int i = 0; i < 4; i++)
        #pragma unroll
        for (int j = 0; j < 2; j++) {
            float2 f = unpk(acc[i][j]);
            int r = m0 + ty*4 + i, c = n0 + tx*4 + 2*j;
            g_part[blockIdx.z * BH + r*Hh + c]     = f.x;
            g_part[blockIdx.z * BH + r*Hh + c + 1] = f.y;
        }
}

__global__ __launch_bounds__(256) void k_init_reduce(const float* __restrict__ b_in)
{
    int i = blockIdx.x * 256 + threadIdx.x;
    float sum = 0.f;
    #pragma unroll
    for (int z = 0; z < SPLITK; z++) sum += g_part[z * BH + i];
    float v = tanhf(sum + b_in[i & (Hh - 1)]);
    g_h0[i] = v;
    g_h1[i] = v;
    int b = i >> 9, n = i & (Hh - 1);
    g_conc1[b * (2*Hh) + Hh + n] = v;   // h1(-1) = h_init
}

// ---------------- gather embedding into [T*B, E] (row = t*B+b) ----------------
__global__ __launch_bounds__(256) void k_gather(const float* __restrict__ emb,
                                                const int* __restrict__ tok)
{
    int idx = blockIdx.x * 256 + threadIdx.x;
    int r   = idx >> 7;
    int e4  = (idx & 127) * 4;
    int t   = r >> 7;
    int b   = r & 127;
    int token = tok[b * Tt + t];
    float4 v = *reinterpret_cast<const float4*>(&emb[token * Ee + e4]);
    *reinterpret_cast<float4*>(&g_xemb[r * Ee + e4]) = v;
}

// ---------------- layer0 x-projections for all timesteps ----------------
__global__ __launch_bounds__(256) void k_xpre(const float* __restrict__ Wu0x,
                                              const float* __restrict__ Wr0x,
                                              const float* __restrict__ Wc0x,
                                              const float* __restrict__ bu0,
                                              const float* __restrict__ br0,
                                              const float* __restrict__ bc0)
{
    __shared__ SmemT<64,64> s;
    u64 acc[4][2] = {};
    const int m0 = blockIdx.y * 64, n0 = blockIdx.x * 64;
    const int ty = threadIdx.x >> 4, tx = threadIdx.x & 15;
    int z = blockIdx.z;
    const float* W  = (z == 0) ? Wu0x : (z == 1) ? Wr0x : Wc0x;
    const float* bi = (z == 0) ? bu0  : (z == 1) ? br0  : bc0;
    float* out      = (z == 0) ? g_Xu0 : (z == 1) ? g_Xr0 : g_Xc0;
    gemm_core2<64,64>(g_xemb, Ee, W, Hh, Hh, 0, Ee, m0, n0, acc, s);
    #pragma unroll
    for (int i = 0; i < 4; i++)
        #pragma unroll
        for (int j = 0; j < 2; j++) {
            float2 f = unpk(acc[i][j]);
            int r = m0 + ty*4 + i, c = n0 + tx*4 + 2*j;
            out[r*Hh + c]     = f.x + bi[c];
            out[r*Hh + c + 1] = f.y + bi[c + 1];
        }
}

// ---------------- wave ur: z=0 layer0 gates t=w; z=1 layer1 gates t=w-1 ----------------
__global__ __launch_bounds__(256) void k_ur(int w,
                                            const float* __restrict__ Wu0h,
                                            const float* __restrict__ Wr0h,
                                            const float* __restrict__ Wu1,
                                            const float* __restrict__ Wr1,
                                            const float* __restrict__ bu1,
                                            const float* __restrict__ br1)
{
    __shared__ SmemT<32,64> s;
    u64 acc[2][2] = {};
    const int m0 = blockIdx.y * 32;
    const int n0g = blockIdx.x * 64;          // 0..1023 virtual N (u | r)
    const int ty = threadIdx.x >> 4, tx = threadIdx.x & 15;
    const int z = blockIdx.z;
    const bool isU = (n0g < Hh);
    const int nloc = isU ? n0g : n0g - Hh;

    if (z == 0) {
        if (w >= Tt) return;
        const float* W = isU ? Wu0h : Wr0h;
        const float* X = (isU ? g_Xu0 : g_Xr0) + w * BH;
        gemm_core2<32,64>(g_h0, Hh, W, Hh, Hh, 0, Hh, m0, nloc, acc, s);
        #pragma unroll
        for (int i = 0; i < 2; i++)
            #pragma unroll
            for (int j = 0; j < 2; j++) {
                float2 f = unpk(acc[i][j]);
                int r = m0 + ty*2 + i, c = nloc + tx*4 + 2*j;
                int idx = r*Hh + c;
                float s0 = sigmoidf_(f.x + X[idx]);
                float s1 = sigmoidf_(f.y + X[idx + 1]);
                if (isU) { g_u0[idx] = s0; g_u0[idx+1] = s1; }
                else     { g_rh0[idx] = s0 * g_h0[idx]; g_rh0[idx+1] = s1 * g_h0[idx+1]; }
            }
    } else {
        if (w == 0) return;
        const float* W  = isU ? Wu1 : Wr1;
        const float* bi = isU ? bu1 : br1;
        float* c2 = g_conc2[(w - 1) & 1];
        gemm_core2<32,64>(g_conc1, 2*Hh, W, Hh, Hh, 0, 2*Hh, m0, nloc, acc, s);
        #pragma unroll
        for (int i = 0; i < 2; i++)
            #pragma unroll
            for (int j = 0; j < 2; j++) {
                float2 f = unpk(acc[i][j]);
                int r = m0 + ty*2 + i, c = nloc + tx*4 + 2*j;
                int idx = r*Hh + c;
                float s0 = sigmoidf_(f.x + bi[c]);
                float s1 = sigmoidf_(f.y + bi[c + 1]);
                if (isU) { g_u1[idx] = s0; g_u1[idx+1] = s1; }
                else {
                    c2[r*(2*Hh) + Hh + c]     = s0 * g_h1[idx];
                    c2[r*(2*Hh) + Hh + c + 1] = s1 * g_h1[idx+1];
                }
            }
    }
}

// ---------------- wave c: z=0 layer0 cand+update t=w; z=1 layer1 t=w-1 ----------------
__global__ __launch_bounds__(256) void k_c(int w,
                                           const float* __restrict__ Wc0h,
                                           const float* __restrict__ Wc1,
                                           const float* __restrict__ bc1)
{
    __shared__ SmemT<32,32> s;
    u64 acc[2][1] = {};
    const int m0 = blockIdx.y * 32, n0 = blockIdx.x * 32;
    const int ty = threadIdx.x >> 4, tx = threadIdx.x & 15;
    const int z = blockIdx.z;

    if (z == 0) {
        if (w >= Tt) return;
        gemm_core2<32,32>(g_rh0, Hh, Wc0h, Hh, Hh, 0, Hh, m0, n0, acc, s);
        const float* Xc = g_Xc0 + w * BH;
        float* c2 = g_conc2[w & 1];
        #pragma unroll
        for (int i = 0; i < 2; i++) {
            float2 f = unpk(acc[i][0]);
            int r = m0 + ty*2 + i, c = n0 + tx*2;
            int idx = r*Hh + c;
            #pragma unroll
            for (int e = 0; e < 2; e++) {
                float cand = tanhf(((e == 0) ? f.x : f.y) + Xc[idx + e]);
                float u = g_u0[idx + e], h = g_h0[idx + e];
                float hn = u * h + (1.0f - u) * cand;
                g_h0[idx + e] = hn;
                g_conc1[r*(2*Hh) + c + e] = hn;
                c2[r*(2*Hh) + c + e] = hn;
            }
        }
    } else {
        if (w == 0) return;
        const float* A = g_conc2[(w - 1) & 1];
        gemm_core2<32,32>(A, 2*Hh, Wc1, Hh, Hh, 0, 2*Hh, m0, n0, acc, s);
        #pragma unroll
        for (int i = 0; i < 2; i++) {
            float2 f = unpk(acc[i][0]);
            int r = m0 + ty*2 + i, c = n0 + tx*2;
            int idx = r*Hh + c;
            #pragma unroll
            for (int e = 0; e < 2; e++) {
                float cand = tanhf(((e == 0) ? f.x : f.y) + bc1[c + e]);
                float u = g_u1[idx + e], h = g_h1[idx + e];
                float hn = u * h + (1.0f - u) * cand;
                g_h1[idx + e] = hn;
                g_conc1[r*(2*Hh) + Hh + c + e] = hn;
                g_X1[(w - 1) * BH + idx + e] = hn;
            }
        }
    }
}

// ---------------- deferred logits: [T*B, H] @ [H, V] ----------------
__global__ __launch_bounds__(256) void k_logits(const float* __restrict__ Wout,
                                                const float* __restrict__ bout,
                                                float* __restrict__ out)
{
    __shared__ SmemT<64,64> s;
    u64 acc[4][2] = {};
    const int m0 = blockIdx.y * 64, n0 = blockIdx.x * 64;
    const int ty = threadIdx.x >> 4, tx = threadIdx.x & 15;
    gemm_core2<64,64>(g_X1, Hh, Wout, Vv, Vv, 0, Hh, m0, n0, acc, s);
    #pragma unroll
    for (int i = 0; i < 4; i++)
        #pragma unroll
        for (int j = 0; j < 2; j++) {
            float2 f = unpk(acc[i][j]);
            int r = m0 + ty*4 + i, c = n0 + tx*4 + 2*j;
            int t = r >> 7, b = r & 127;
            long long base = ((long long)(b * Tt + t)) * Vv;
            if (c < Vv)     out[base + c]     = f.x + bout[c];
            if (c + 1 < Vv) out[base + c + 1] = f.y + bout[c + 1];
        }
}

// ---------------- final states into output tail ----------------
__global__ __launch_bounds__(256) void k_final(float* __restrict__ out)
{
    int i = blockIdx.x * 256 + threadIdx.x;
    int l = i >> 16;
    int j = i & (BH - 1);
    out[(long long)Bb * Tt * Vv + i] = l ? g_h1[j] : g_h0[j];
}

// ---------------- launch ----------------
extern "C" void kernel_launch(void* const* d_in, const int* in_sizes, int n_in,
                              void* d_out, int out_size)
{
    const float* vgg   = (const float*)d_in[0];
    const int*   xTok  = (const int*)  d_in[1];
    const float* emb   = (const float*)d_in[2];
    const float* W_in  = (const float*)d_in[3];
    const float* b_in  = (const float*)d_in[4];
    const float* Wu    = (const float*)d_in[5];
    const float* bu    = (const float*)d_in[6];
    const float* Wr    = (const float*)d_in[7];
    const float* br    = (const float*)d_in[8];
    const float* Wc    = (const float*)d_in[9];
    const float* bc    = (const float*)d_in[10];
    const float* W_out = (const float*)d_in[11];
    const float* b_out = (const float*)d_in[12];
    float* out = (float*)d_out;

    const float* Wu0x = Wu;                const float* Wu0h = Wu + Ee * Hh;
    const float* Wr0x = Wr;                const float* Wr0h = Wr + Ee * Hh;
    const float* Wc0x = Wc;                const float* Wc0h = Wc + Ee * Hh;
    const float* Wu1  = Wu + (Ee + Hh) * Hh;
    const float* Wr1  = Wr + (Ee + Hh) * Hh;
    const float* Wc1  = Wc + (Ee + Hh) * Hh;
    const float* bu1  = bu + Hh;
    const float* br1  = br + Hh;
    const float* bc1  = bc + Hh;

    // init hidden state
    k_init_part<<<dim3(Hh/64, Bb/64, SPLITK), 256>>>(vgg, W_in);
    k_init_reduce<<<BH/256, 256>>>(b_in);

    // gather embeddings + precompute layer0 x-projections
    k_gather<<<(Tt * Bb * (Ee/4)) / 256, 256>>>(emb, xTok);
    k_xpre<<<dim3(Hh/64, (Tt*Bb)/64, 3), 256>>>(Wu0x, Wr0x, Wc0x, bu, br, bc);

    // pipelined wavefront scan: wave w runs layer0@t=w and layer1@t=w-1
    for (int w = 0; w <= Tt; w++) {
        k_ur<<<dim3(2*Hh/64, Bb/32, 2), 256>>>(w, Wu0h, Wr0h, Wu1, Wr1, bu1, br1);
        k_c <<<dim3(Hh/32,   Bb/32, 2), 256>>>(w, Wc0h, Wc1, bc1);
    }

    // deferred big logits GEMM + final states
    k_logits<<<dim3((Vv + 63)/64, (Tt*Bb)/64), 256>>>(W_out, b_out, out);
    k_final<<<(2*BH)/256, 256>>>(out);
}

// round 4
// speedup vs baseline: 2.0091x; 1.6831x over previous
#include <cuda_runtime.h>
#include <cuda_bf16.h>
#include <math.h>
#include <stdint.h>

#define Bb 128
#define Tt 30
#define Vv 10000
#define Ee 512
#define Hh 512
#define Ff 4096
#define BH (Bb*Hh)          // 65536
#define TBH (Tt*Bb*Hh)      // 1966080
#define Vpad 10112          // 79*128
#define SZGRU (512*1024)

typedef __nv_bfloat16 bf16;

// ---------------- fp32 state / precomputed projections ----------------
__device__ float g_h0f[BH], g_h1f[BH], g_u0f[BH], g_u1f[BH];
__device__ float g_Xu0[TBH], g_Xr0[TBH], g_Xc0[TBH];

// ---------------- bf16 hi/lo split activations (GEMM A operands) ----------------
__device__ __align__(16) bf16 g_vgg_h[Bb*Ff],  g_vgg_l[Bb*Ff];
__device__ __align__(16) bf16 g_xemb_h[TBH],   g_xemb_l[TBH];
__device__ __align__(16) bf16 g_h0h[BH],       g_h0l[BH];
__device__ __align__(16) bf16 g_rh0h[BH],      g_rh0l[BH];
__device__ __align__(16) bf16 g_c1h[Bb*1024],  g_c1l[Bb*1024];
__device__ __align__(16) bf16 g_c2h[2][Bb*1024], g_c2l[2][Bb*1024];
__device__ __align__(16) bf16 g_X1h[TBH],      g_X1l[TBH];

// ---------------- bf16 hi/lo split weights, transposed to [N, K] ----------------
__device__ __align__(16) bf16 g_Win_h[Hh*Ff],     g_Win_l[Hh*Ff];
__device__ __align__(16) bf16 g_Wgru_h[6*SZGRU],  g_Wgru_l[6*SZGRU];
__device__ __align__(16) bf16 g_Wout_h[Vpad*Hh],  g_Wout_l[Vpad*Hh];

// ---------------- helpers ----------------
__device__ __forceinline__ uint32_t smem_u32(const void* p) {
    uint32_t a;
    asm("{ .reg .u64 t; cvta.to.shared.u64 t, %1; cvt.u32.u64 %0, t; }" : "=r"(a) : "l"(p));
    return a;
}
__device__ __forceinline__ void cpasync16(uint32_t dst, const void* src) {
    asm volatile("cp.async.cg.shared.global [%0], [%1], 16;" :: "r"(dst), "l"(src) : "memory");
}
#define CP_COMMIT() asm volatile("cp.async.commit_group;" ::: "memory")
#define CP_WAIT1()  asm volatile("cp.async.wait_group 1;" ::: "memory")
#define CP_WAIT0()  asm volatile("cp.async.wait_group 0;" ::: "memory")

#define LDSM4(R, addr) \
    asm volatile("ldmatrix.sync.aligned.m8n8.x4.shared.b16 {%0,%1,%2,%3}, [%4];" \
        : "=r"((R)[0]), "=r"((R)[1]), "=r"((R)[2]), "=r"((R)[3]) : "r"(addr))

__device__ __forceinline__ void mmaop(float* c, const uint32_t* a, const uint32_t* b) {
    asm volatile("mma.sync.aligned.m16n8k16.row.col.f32.bf16.bf16.f32 "
        "{%0,%1,%2,%3}, {%4,%5,%6,%7}, {%8,%9}, {%0,%1,%2,%3};"
        : "+f"(c[0]), "+f"(c[1]), "+f"(c[2]), "+f"(c[3])
        : "r"(a[0]), "r"(a[1]), "r"(a[2]), "r"(a[3]), "r"(b[0]), "r"(b[1]));
}

__device__ __forceinline__ void splitbf(float x, bf16& h, bf16& l) {
    h = __float2bfloat16(x);
    l = __float2bfloat16(x - __bfloat162float(h));
}
__device__ __forceinline__ float sigmoidf_(float x) { return 1.0f / (1.0f + expf(-x)); }

// ---------------- mma.sync split-3 GEMM core ----------------
// D[128 x TN] = A[128,K] @ B[N,K]^T   (A,B bf16 hi/lo; fp32 acc; 3-term Markidis)
// 256 threads = 8 warps as 2x4. Warp tile 64 x TN/4. K-tile 32, cp.async 2-buf.
// smem row pitch 80B (conflict-free ldmatrix). epi(globalRow, globalCol, value).
#define ROWB 80
#define ASZ (128*ROWB)
template<int TN, typename Epi>
__device__ __forceinline__ void mma_gemm(
    const bf16* __restrict__ Ah, const bf16* __restrict__ Al, int lda, int m0,
    const bf16* __restrict__ Bh, const bf16* __restrict__ Bl, int ldb, int n0,
    int K, Epi epi)
{
    extern __shared__ char smem[];
    constexpr int BSZ = TN * ROWB;
    constexpr int BUF = 2*ASZ + 2*BSZ;
    const uint32_t s0 = smem_u32(smem);

    const int tid = threadIdx.x, lane = tid & 31, wid = tid >> 5;
    const int wm = wid >> 2, wn = wid & 3;
    constexpr int WN = TN / 4;
    constexpr int NF = WN / 8;

    float acc[4][NF][4] = {};

    auto issue = [&](int ch, int b) {
        uint32_t d = s0 + b * BUF;
        int k0 = ch * 32;
        #pragma unroll
        for (int i = 0; i < 2; i++) {
            int v = tid + i * 256; int row = v >> 2, c = v & 3;
            const bf16* sh = Ah + (m0 + row) * lda + k0 + c * 8;
            const bf16* sl = Al + (m0 + row) * lda + k0 + c * 8;
            cpasync16(d + row * ROWB + c * 16, sh);
            cpasync16(d + ASZ + row * ROWB + c * 16, sl);
        }
        #pragma unroll
        for (int i = 0; i < (TN * 4) / 256; i++) {
            int v = tid + i * 256; int row = v >> 2, c = v & 3;
            cpasync16(d + 2*ASZ + row * ROWB + c * 16,       Bh + (n0 + row) * ldb + k0 + c * 8);
            cpasync16(d + 2*ASZ + BSZ + row * ROWB + c * 16, Bl + (n0 + row) * ldb + k0 + c * 8);
        }
        CP_COMMIT();
    };

    const int lrow = lane & 15, lhalf = lane >> 4;
    const int NC = K / 32;

    issue(0, 0);
    for (int ch = 0; ch < NC; ch++) {
        int b = ch & 1;
        if (ch + 1 < NC) { issue(ch + 1, (ch + 1) & 1); CP_WAIT1(); }
        else CP_WAIT0();
        __syncthreads();
        uint32_t d = s0 + b * BUF;
        #pragma unroll
        for (int kk = 0; kk < 2; kk++) {
            uint32_t ah[4][4], al[4][4], bh[NF][2], bl[NF][2];
            #pragma unroll
            for (int f = 0; f < 4; f++) {
                uint32_t addr = d + (wm*64 + f*16 + lrow) * ROWB + lhalf*16 + kk*32;
                LDSM4(ah[f], addr);
                LDSM4(al[f], addr + ASZ);
            }
            #pragma unroll
            for (int g = 0; g < NF; g += 2) {
                uint32_t addr = d + 2*ASZ + (wn*WN + g*8 + lrow) * ROWB + lhalf*16 + kk*32;
                uint32_t t4[4];
                LDSM4(t4, addr);
                bh[g][0] = t4[0]; bh[g][1] = t4[2];
                bh[g+1][0] = t4[1]; bh[g+1][1] = t4[3];
                LDSM4(t4, addr + BSZ);
                bl[g][0] = t4[0]; bl[g][1] = t4[2];
                bl[g+1][0] = t4[1]; bl[g+1][1] = t4[3];
            }
            #pragma unroll
            for (int f = 0; f < 4; f++)
                #pragma unroll
                for (int g = 0; g < NF; g++) {
                    mmaop(acc[f][g], ah[f], bh[g]);
                    mmaop(acc[f][g], ah[f], bl[g]);
                    mmaop(acc[f][g], al[f], bh[g]);
                }
        }
        __syncthreads();
    }

    #pragma unroll
    for (int f = 0; f < 4; f++)
        #pragma unroll
        for (int g = 0; g < NF; g++) {
            int r0 = m0 + wm*64 + f*16 + (lane >> 2);
            int c0 = n0 + wn*WN + g*8 + (lane & 3) * 2;
            epi(r0,     c0,     acc[f][g][0]);
            epi(r0,     c0 + 1, acc[f][g][1]);
            epi(r0 + 8, c0,     acc[f][g][2]);
            epi(r0 + 8, c0 + 1, acc[f][g][3]);
        }
}

#define SMEM128 (2 * (2*ASZ + 2*128*ROWB))   // 81920
#define SMEM64  (2 * (2*ASZ + 2*64*ROWB))    // 61440

// ---------------- prepack: transpose fp32 [K,N] -> bf16 hi/lo [Npad,K] ----------------
__global__ __launch_bounds__(256) void pk_T(const float* __restrict__ src,
                                            bf16* __restrict__ dh, bf16* __restrict__ dl,
                                            int K, int N, int Npad)
{
    __shared__ float tile[32][33];
    int kb = blockIdx.y * 32, nb = blockIdx.x * 32;
    int tx = threadIdx.x & 31, ty = threadIdx.x >> 5;
    #pragma unroll
    for (int i = ty; i < 32; i += 8) {
        int n = nb + tx;
        tile[i][tx] = (n < N) ? src[(kb + i) * N + n] : 0.f;
    }
    __syncthreads();
    #pragma unroll
    for (int i = ty; i < 32; i += 8) {
        int n = nb + i, k = kb + tx;
        if (n < Npad) {
            bf16 h, l; splitbf(tile[tx][i], h, l);
            dh[n * K + k] = h; dl[n * K + k] = l;
        }
    }
}

// ---------------- prepack: elementwise split of vgg ----------------
__global__ __launch_bounds__(256) void pk_vgg(const float* __restrict__ src)
{
    int i = blockIdx.x * 256 + threadIdx.x;
    bf16 h, l; splitbf(src[i], h, l);
    g_vgg_h[i] = h; g_vgg_l[i] = l;
}

// ---------------- gather embedding -> bf16 split [T*B, E] ----------------
__global__ __launch_bounds__(256) void k_gather(const float* __restrict__ emb,
                                                const int* __restrict__ tok)
{
    int idx = blockIdx.x * 256 + threadIdx.x;   // over T*B*E
    int r = idx >> 9, e = idx & 511;
    int t = r >> 7, b = r & 127;
    int token = tok[b * Tt + t];
    bf16 h, l; splitbf(emb[token * Ee + e], h, l);
    g_xemb_h[idx] = h; g_xemb_l[idx] = l;
}

// ---------------- init: h = tanh(vgg @ W_in + b_in) ----------------
__global__ __launch_bounds__(256, 1) void k_init(const float* __restrict__ b_in)
{
    int n0 = blockIdx.x * 128;
    mma_gemm<128>(g_vgg_h, g_vgg_l, Ff, 0, g_Win_h, g_Win_l, Ff, n0, Ff,
        [&] (int r, int c, float v) {
            float x = tanhf(v + b_in[c]);
            int idx = r * Hh + c;
            g_h0f[idx] = x; g_h1f[idx] = x;
            bf16 h, l; splitbf(x, h, l);
            g_h0h[idx] = h; g_h0l[idx] = l;
            int ci = r * 1024 + Hh + c;
            g_c1h[ci] = h; g_c1l[ci] = l;
        });
}

// ---------------- layer0 x-projections (all T), +bias ----------------
__global__ __launch_bounds__(256, 1) void k_xpre(const float* __restrict__ bu,
                                                 const float* __restrict__ br,
                                                 const float* __restrict__ bc)
{
    int n0 = blockIdx.x * 128, m0 = blockIdx.y * 128, gate = blockIdx.z;
    const bf16* Bh = g_Wgru_h + gate * SZGRU;
    const bf16* Bl = g_Wgru_l + gate * SZGRU;
    const float* bi = (gate == 0) ? bu : (gate == 1) ? br : bc;
    float* out = (gate == 0) ? g_Xu0 : (gate == 1) ? g_Xr0 : g_Xc0;
    mma_gemm<128>(g_xemb_h, g_xemb_l, Hh, m0, Bh, Bl, 1024, n0, Hh,
        [&] (int r, int c, float v) {
            out[r * Hh + c] = v + bi[c];
        });
}

// ---------------- wave ur: z=0 layer0 gates @t=w ; z=1 layer1 gates @t=w-1 ----------------
__global__ __launch_bounds__(256, 1) void k_ur(int w,
                                               const float* __restrict__ bu1,
                                               const float* __restrict__ br1)
{
    int gate = blockIdx.y, z = blockIdx.z;
    if (z == 0 && w >= Tt) return;
    if (z == 1 && w == 0) return;
    int n0 = blockIdx.x * 64;

    if (z == 0) {
        const bf16* Bh = g_Wgru_h + gate * SZGRU + 512;   // h-part of layer0 W
        const bf16* Bl = g_Wgru_l + gate * SZGRU + 512;
        const float* X = (gate ? g_Xr0 : g_Xu0) + w * BH;
        mma_gemm<64>(g_h0h, g_h0l, Hh, 0, Bh, Bl, 1024, n0, Hh,
            [&] (int r, int c, float v) {
                int idx = r * Hh + c;
                float sv = sigmoidf_(v + X[idx]);
                if (gate == 0) g_u0f[idx] = sv;
                else {
                    float rh = sv * g_h0f[idx];
                    bf16 h, l; splitbf(rh, h, l);
                    g_rh0h[idx] = h; g_rh0l[idx] = l;
                }
            });
    } else {
        const bf16* Bh = g_Wgru_h + (3 + gate) * SZGRU;
        const bf16* Bl = g_Wgru_l + (3 + gate) * SZGRU;
        const float* bi = gate ? br1 : bu1;
        int par = (w - 1) & 1;
        mma_gemm<64>(g_c1h, g_c1l, 1024, 0, Bh, Bl, 1024, n0, 1024,
            [&] (int r, int c, float v) {
                int idx = r * Hh + c;
                float sv = sigmoidf_(v + bi[c]);
                if (gate == 0) g_u1f[idx] = sv;
                else {
                    float rh = sv * g_h1f[idx];
                    bf16 h, l; splitbf(rh, h, l);
                    int ci = r * 1024 + Hh + c;
                    g_c2h[par][ci] = h; g_c2l[par][ci] = l;
                }
            });
    }
}

// ---------------- wave c: z=0 layer0 cand+update @t=w ; z=1 layer1 @t=w-1 ----------------
__global__ __launch_bounds__(256, 1) void k_c(int w, const float* __restrict__ bc1)
{
    int z = blockIdx.z;
    if (z == 0 && w >= Tt) return;
    if (z == 1 && w == 0) return;
    int n0 = blockIdx.x * 64;

    if (z == 0) {
        const bf16* Bh = g_Wgru_h + 2 * SZGRU + 512;
        const bf16* Bl = g_Wgru_l + 2 * SZGRU + 512;
        const float* Xc = g_Xc0 + w * BH;
        int par = w & 1;
        mma_gemm<64>(g_rh0h, g_rh0l, Hh, 0, Bh, Bl, 1024, n0, Hh,
            [&] (int r, int c, float v) {
                int idx = r * Hh + c;
                float cand = tanhf(v + Xc[idx]);
                float u = g_u0f[idx], hv = g_h0f[idx];
                float hn = u * hv + (1.0f - u) * cand;
                g_h0f[idx] = hn;
                bf16 h, l; splitbf(hn, h, l);
                g_h0h[idx] = h; g_h0l[idx] = l;
                int ci = r * 1024 + c;
                g_c1h[ci] = h; g_c1l[ci] = l;
                g_c2h[par][ci] = h; g_c2l[par][ci] = l;
            });
    } else {
        int par = (w - 1) & 1;
        const bf16* Bh = g_Wgru_h + 5 * SZGRU;
        const bf16* Bl = g_Wgru_l + 5 * SZGRU;
        mma_gemm<64>(g_c2h[par], g_c2l[par], 1024, 0, Bh, Bl, 1024, n0, 1024,
            [&] (int r, int c, float v) {
                int idx = r * Hh + c;
                float cand = tanhf(v + bc1[c]);
                float u = g_u1f[idx], hv = g_h1f[idx];
                float hn = u * hv + (1.0f - u) * cand;
                g_h1f[idx] = hn;
                bf16 h, l; splitbf(hn, h, l);
                g_c1h[r * 1024 + Hh + c] = h;
                g_c1l[r * 1024 + Hh + c] = l;
                int xi = ((w - 1) * Bb + r) * Hh + c;
                g_X1h[xi] = h; g_X1l[xi] = l;
            });
    }
}

// ---------------- logits: [T*B, H] @ W_out[H, V] ----------------
__global__ __launch_bounds__(256, 1) void k_logits(const float* __restrict__ bout,
                                                   float* __restrict__ out)
{
    int n0 = blockIdx.x * 128, m0 = blockIdx.y * 128;
    mma_gemm<128>(g_X1h, g_X1l, Hh, m0, g_Wout_h, g_Wout_l, Hh, n0, Hh,
        [&] (int r, int c, float v) {
            if (c < Vv) {
                int t = r >> 7, b = r & 127;
                out[(long long)(b * Tt + t) * Vv + c] = v + bout[c];
            }
        });
}

// ---------------- final states into output tail ----------------
__global__ __launch_bounds__(256) void k_final(float* __restrict__ out)
{
    int i = blockIdx.x * 256 + threadIdx.x;
    int l = i >> 16;
    int j = i & (BH - 1);
    out[(long long)Bb * Tt * Vv + i] = l ? g_h1f[j] : g_h0f[j];
}

// ---------------- launch ----------------
extern "C" void kernel_launch(void* const* d_in, const int* in_sizes, int n_in,
                              void* d_out, int out_size)
{
    const float* vgg   = (const float*)d_in[0];
    const int*   xTok  = (const int*)  d_in[1];
    const float* emb   = (const float*)d_in[2];
    const float* W_in  = (const float*)d_in[3];
    const float* b_in  = (const float*)d_in[4];
    const float* Wu    = (const float*)d_in[5];
    const float* bu    = (const float*)d_in[6];
    const float* Wr    = (const float*)d_in[7];
    const float* br    = (const float*)d_in[8];
    const float* Wc    = (const float*)d_in[9];
    const float* bc    = (const float*)d_in[10];
    const float* W_out = (const float*)d_in[11];
    const float* b_out = (const float*)d_in[12];
    float* out = (float*)d_out;

    static int attr_done = 0;
    cudaFuncSetAttribute(k_init,   cudaFuncAttributeMaxDynamicSharedMemorySize, SMEM128);
    cudaFuncSetAttribute(k_xpre,   cudaFuncAttributeMaxDynamicSharedMemorySize, SMEM128);
    cudaFuncSetAttribute(k_logits, cudaFuncAttributeMaxDynamicSharedMemorySize, SMEM128);
    cudaFuncSetAttribute(k_ur,     cudaFuncAttributeMaxDynamicSharedMemorySize, SMEM64);
    cudaFuncSetAttribute(k_c,      cudaFuncAttributeMaxDynamicSharedMemorySize, SMEM64);
    (void)attr_done;

    // ---- prepack weights (transpose + bf16 split) ----
    bf16 *Wgh, *Wgl, *Wih, *Wil, *Woh, *Wol;
    cudaGetSymbolAddress((void**)&Wgh, g_Wgru_h);
    cudaGetSymbolAddress((void**)&Wgl, g_Wgru_l);
    cudaGetSymbolAddress((void**)&Wih, g_Win_h);
    cudaGetSymbolAddress((void**)&Wil, g_Win_l);
    cudaGetSymbolAddress((void**)&Woh, g_Wout_h);
    cudaGetSymbolAddress((void**)&Wol, g_Wout_l);

    pk_vgg<<<(Bb * Ff) / 256, 256>>>(vgg);
    pk_T<<<dim3(16, 128), 256>>>(W_in, Wih, Wil, Ff, Hh, Hh);
    pk_T<<<dim3(16, 32), 256>>>(Wu,            Wgh + 0*SZGRU, Wgl + 0*SZGRU, 1024, Hh, Hh);
    pk_T<<<dim3(16, 32), 256>>>(Wr,            Wgh + 1*SZGRU, Wgl + 1*SZGRU, 1024, Hh, Hh);
    pk_T<<<dim3(16, 32), 256>>>(Wc,            Wgh + 2*SZGRU, Wgl + 2*SZGRU, 1024, Hh, Hh);
    pk_T<<<dim3(16, 32), 256>>>(Wu + 1024*Hh,  Wgh + 3*SZGRU, Wgl + 3*SZGRU, 1024, Hh, Hh);
    pk_T<<<dim3(16, 32), 256>>>(Wr + 1024*Hh,  Wgh + 4*SZGRU, Wgl + 4*SZGRU, 1024, Hh, Hh);
    pk_T<<<dim3(16, 32), 256>>>(Wc + 1024*Hh,  Wgh + 5*SZGRU, Wgl + 5*SZGRU, 1024, Hh, Hh);
    pk_T<<<dim3(Vpad / 32, 16), 256>>>(W_out, Woh, Wol, Hh, Vv, Vpad);

    // ---- init + embeddings + x-projections ----
    k_init<<<4, 256, SMEM128>>>(b_in);
    k_gather<<<TBH / 256, 256>>>(emb, xTok);
    k_xpre<<<dim3(4, Tt * Bb / 128, 3), 256, SMEM128>>>(bu, br, bc);

    // ---- pipelined wavefront scan ----
    const float* bu1 = bu + Hh;
    const float* br1 = br + Hh;
    const float* bc1 = bc + Hh;
    for (int w = 0; w <= Tt; w++) {
        k_ur<<<dim3(8, 2, 2), 256, SMEM64>>>(w, bu1, br1);
        k_c <<<dim3(8, 1, 2), 256, SMEM64>>>(w, bc1);
    }

    // ---- deferred logits + final state ----
    k_logits<<<dim3(Vpad / 128, Tt * Bb / 128), 256, SMEM128>>>(b_out, out);
    k_final<<<(2 * BH) / 256, 256>>>(out);
}

// round 5
// speedup vs baseline: 2.0130x; 1.0019x over previous
#include <cuda_runtime.h>
#include <cuda_bf16.h>
#include <math.h>
#include <stdint.h>

#define Bb 128
#define Tt 30
#define Vv 10000
#define Ee 512
#define Hh 512
#define Ff 4096
#define BH (Bb*Hh)          // 65536
#define TBH (Tt*Bb*Hh)      // 1966080
#define Vpad 10112          // 79*128
#define SZGRU (512*1024)

typedef __nv_bfloat16 bf16;

// ---------------- fp32 state / precomputed projections ----------------
__device__ float g_h0f[BH], g_h1f[BH], g_u0f[BH], g_u1f[BH];
__device__ float g_Xu0[TBH], g_Xr0[TBH], g_Xc0[TBH];

// ---------------- bf16 hi/lo split activations (GEMM A operands) ----------------
__device__ __align__(16) bf16 g_vgg_h[Bb*Ff],  g_vgg_l[Bb*Ff];
__device__ __align__(16) bf16 g_xemb_h[TBH],   g_xemb_l[TBH];
__device__ __align__(16) bf16 g_h0h[BH],       g_h0l[BH];
__device__ __align__(16) bf16 g_rh0h[BH],      g_rh0l[BH];
__device__ __align__(16) bf16 g_c1h[Bb*1024],  g_c1l[Bb*1024];
__device__ __align__(16) bf16 g_c2h[2][Bb*1024], g_c2l[2][Bb*1024];
__device__ __align__(16) bf16 g_X1h[TBH],      g_X1l[TBH];

// ---------------- bf16 hi/lo split weights, transposed to [N, K] ----------------
__device__ __align__(16) bf16 g_Win_h[Hh*Ff],     g_Win_l[Hh*Ff];
__device__ __align__(16) bf16 g_Wgru_h[6*SZGRU],  g_Wgru_l[6*SZGRU];
__device__ __align__(16) bf16 g_Wout_h[Vpad*Hh],  g_Wout_l[Vpad*Hh];

// ---------------- helpers ----------------
__device__ __forceinline__ uint32_t smem_u32(const void* p) {
    uint32_t a;
    asm("{ .reg .u64 t; cvta.to.shared.u64 t, %1; cvt.u32.u64 %0, t; }" : "=r"(a) : "l"(p));
    return a;
}
__device__ __forceinline__ void cpasync16(uint32_t dst, const void* src) {
    asm volatile("cp.async.cg.shared.global [%0], [%1], 16;" :: "r"(dst), "l"(src) : "memory");
}
#define CP_COMMIT() asm volatile("cp.async.commit_group;" ::: "memory")
#define CP_WAIT1()  asm volatile("cp.async.wait_group 1;" ::: "memory")
#define CP_WAIT0()  asm volatile("cp.async.wait_group 0;" ::: "memory")

#define LDSM4(R, addr) \
    asm volatile("ldmatrix.sync.aligned.m8n8.x4.shared.b16 {%0,%1,%2,%3}, [%4];" \
        : "=r"((R)[0]), "=r"((R)[1]), "=r"((R)[2]), "=r"((R)[3]) : "r"(addr))

__device__ __forceinline__ void mmaop(float* c, const uint32_t* a, const uint32_t* b) {
    asm volatile("mma.sync.aligned.m16n8k16.row.col.f32.bf16.bf16.f32 "
        "{%0,%1,%2,%3}, {%4,%5,%6,%7}, {%8,%9}, {%0,%1,%2,%3};"
        : "+f"(c[0]), "+f"(c[1]), "+f"(c[2]), "+f"(c[3])
        : "r"(a[0]), "r"(a[1]), "r"(a[2]), "r"(a[3]), "r"(b[0]), "r"(b[1]));
}

__device__ __forceinline__ void splitbf(float x, bf16& h, bf16& l) {
    h = __float2bfloat16(x);
    l = __float2bfloat16(x - __bfloat162float(h));
}
__device__ __forceinline__ float sigmoidf_(float x) { return 1.0f / (1.0f + expf(-x)); }

// ---------------- mma.sync split-3 GEMM core ----------------
// D[128 x TN] = A[128,K] @ B[N,K]^T   (A,B bf16 hi/lo; fp32 acc; 3-term Markidis)
// 256 threads = 8 warps as 2x4. Warp tile 64 x TN/4. K-tile 32, cp.async 2-buf.
// smem row pitch 80B (conflict-free ldmatrix). epi(globalRow, globalCol, value).
#define ROWB 80
#define ASZ (128*ROWB)
template<int TN, typename Epi>
__device__ __forceinline__ void mma_gemm(
    const bf16* __restrict__ Ah, const bf16* __restrict__ Al, int lda, int m0,
    const bf16* __restrict__ Bh, const bf16* __restrict__ Bl, int ldb, int n0,
    int K, Epi epi)
{
    extern __shared__ char smem[];
    constexpr int BSZ = TN * ROWB;
    constexpr int BUF = 2*ASZ + 2*BSZ;
    const uint32_t s0 = smem_u32(smem);

    const int tid = threadIdx.x, lane = tid & 31, wid = tid >> 5;
    const int wm = wid >> 2, wn = wid & 3;
    constexpr int WN = TN / 4;
    constexpr int NF = WN / 8;

    float acc[4][NF][4] = {};

    auto issue = [&](int ch, int b) {
        uint32_t d = s0 + b * BUF;
        int k0 = ch * 32;
        #pragma unroll
        for (int i = 0; i < 2; i++) {
            int v = tid + i * 256; int row = v >> 2, c = v & 3;
            const bf16* sh = Ah + (m0 + row) * lda + k0 + c * 8;
            const bf16* sl = Al + (m0 + row) * lda + k0 + c * 8;
            cpasync16(d + row * ROWB + c * 16, sh);
            cpasync16(d + ASZ + row * ROWB + c * 16, sl);
        }
        #pragma unroll
        for (int i = 0; i < (TN * 4) / 256; i++) {
            int v = tid + i * 256; int row = v >> 2, c = v & 3;
            cpasync16(d + 2*ASZ + row * ROWB + c * 16,       Bh + (n0 + row) * ldb + k0 + c * 8);
            cpasync16(d + 2*ASZ + BSZ + row * ROWB + c * 16, Bl + (n0 + row) * ldb + k0 + c * 8);
        }
        CP_COMMIT();
    };

    const int lrow = lane & 15, lhalf = lane >> 4;
    const int NC = K / 32;

    issue(0, 0);
    for (int ch = 0; ch < NC; ch++) {
        int b = ch & 1;
        if (ch + 1 < NC) { issue(ch + 1, (ch + 1) & 1); CP_WAIT1(); }
        else CP_WAIT0();
        __syncthreads();
        uint32_t d = s0 + b * BUF;
        #pragma unroll
        for (int kk = 0; kk < 2; kk++) {
            uint32_t ah[4][4], al[4][4], bh[NF][2], bl[NF][2];
            #pragma unroll
            for (int f = 0; f < 4; f++) {
                uint32_t addr = d + (wm*64 + f*16 + lrow) * ROWB + lhalf*16 + kk*32;
                LDSM4(ah[f], addr);
                LDSM4(al[f], addr + ASZ);
            }
            #pragma unroll
            for (int g = 0; g < NF; g += 2) {
                uint32_t addr = d + 2*ASZ + (wn*WN + g*8 + lrow) * ROWB + lhalf*16 + kk*32;
                uint32_t t4[4];
                LDSM4(t4, addr);
                bh[g][0] = t4[0]; bh[g][1] = t4[2];
                bh[g+1][0] = t4[1]; bh[g+1][1] = t4[3];
                LDSM4(t4, addr + BSZ);
                bl[g][0] = t4[0]; bl[g][1] = t4[2];
                bl[g+1][0] = t4[1]; bl[g+1][1] = t4[3];
            }
            #pragma unroll
            for (int f = 0; f < 4; f++)
                #pragma unroll
                for (int g = 0; g < NF; g++) {
                    mmaop(acc[f][g], ah[f], bh[g]);
                    mmaop(acc[f][g], ah[f], bl[g]);
                    mmaop(acc[f][g], al[f], bh[g]);
                }
        }
        __syncthreads();
    }

    #pragma unroll
    for (int f = 0; f < 4; f++)
        #pragma unroll
        for (int g = 0; g < NF; g++) {
            int r0 = m0 + wm*64 + f*16 + (lane >> 2);
            int c0 = n0 + wn*WN + g*8 + (lane & 3) * 2;
            epi(r0,     c0,     acc[f][g][0]);
            epi(r0,     c0 + 1, acc[f][g][1]);
            epi(r0 + 8, c0,     acc[f][g][2]);
            epi(r0 + 8, c0 + 1, acc[f][g][3]);
        }
}

#define SMEM128 (2 * (2*ASZ + 2*128*ROWB))   // 81920
#define SMEM64  (2 * (2*ASZ + 2*64*ROWB))    // 61440

// ---------------- prepack: transpose fp32 [K,N] -> bf16 hi/lo [Npad,K] ----------------
__global__ __launch_bounds__(256) void pk_T(const float* __restrict__ src,
                                            bf16* __restrict__ dh, bf16* __restrict__ dl,
                                            int K, int N, int Npad)
{
    __shared__ float tile[32][33];
    int kb = blockIdx.y * 32, nb = blockIdx.x * 32;
    int tx = threadIdx.x & 31, ty = threadIdx.x >> 5;
    #pragma unroll
    for (int i = ty; i < 32; i += 8) {
        int n = nb + tx;
        tile[i][tx] = (n < N) ? src[(kb + i) * N + n] : 0.f;
    }
    __syncthreads();
    #pragma unroll
    for (int i = ty; i < 32; i += 8) {
        int n = nb + i, k = kb + tx;
        if (n < Npad) {
            bf16 h, l; splitbf(tile[tx][i], h, l);
            dh[n * K + k] = h; dl[n * K + k] = l;
        }
    }
}

// ---------------- prepack: elementwise split of vgg ----------------
__global__ __launch_bounds__(256) void pk_vgg(const float* __restrict__ src)
{
    int i = blockIdx.x * 256 + threadIdx.x;
    bf16 h, l; splitbf(src[i], h, l);
    g_vgg_h[i] = h; g_vgg_l[i] = l;
}

// ---------------- gather embedding -> bf16 split [T*B, E] ----------------
__global__ __launch_bounds__(256) void k_gather(const float* __restrict__ emb,
                                                const int* __restrict__ tok)
{
    int idx = blockIdx.x * 256 + threadIdx.x;   // over T*B*E
    int r = idx >> 9, e = idx & 511;
    int t = r >> 7, b = r & 127;
    int token = tok[b * Tt + t];
    bf16 h, l; splitbf(emb[token * Ee + e], h, l);
    g_xemb_h[idx] = h; g_xemb_l[idx] = l;
}

// ---------------- init: h = tanh(vgg @ W_in + b_in) ----------------
__global__ __launch_bounds__(256, 1) void k_init(const float* __restrict__ b_in)
{
    int n0 = blockIdx.x * 128;
    mma_gemm<128>(g_vgg_h, g_vgg_l, Ff, 0, g_Win_h, g_Win_l, Ff, n0, Ff,
        [&] (int r, int c, float v) {
            float x = tanhf(v + b_in[c]);
            int idx = r * Hh + c;
            g_h0f[idx] = x; g_h1f[idx] = x;
            bf16 h, l; splitbf(x, h, l);
            g_h0h[idx] = h; g_h0l[idx] = l;
            int ci = r * 1024 + Hh + c;
            g_c1h[ci] = h; g_c1l[ci] = l;
        });
}

// ---------------- layer0 x-projections (all T), +bias ----------------
__global__ __launch_bounds__(256, 1) void k_xpre(const float* __restrict__ bu,
                                                 const float* __restrict__ br,
                                                 const float* __restrict__ bc)
{
    int n0 = blockIdx.x * 128, m0 = blockIdx.y * 128, gate = blockIdx.z;
    const bf16* Bh = g_Wgru_h + gate * SZGRU;
    const bf16* Bl = g_Wgru_l + gate * SZGRU;
    const float* bi = (gate == 0) ? bu : (gate == 1) ? br : bc;
    float* out = (gate == 0) ? g_Xu0 : (gate == 1) ? g_Xr0 : g_Xc0;
    mma_gemm<128>(g_xemb_h, g_xemb_l, Hh, m0, Bh, Bl, 1024, n0, Hh,
        [&] (int r, int c, float v) {
            out[r * Hh + c] = v + bi[c];
        });
}

// ---------------- wave ur: z=0 layer0 gates @t=w ; z=1 layer1 gates @t=w-1 ----------------
__global__ __launch_bounds__(256, 1) void k_ur(int w,
                                               const float* __restrict__ bu1,
                                               const float* __restrict__ br1)
{
    int gate = blockIdx.y, z = blockIdx.z;
    if (z == 0 && w >= Tt) return;
    if (z == 1 && w == 0) return;
    int n0 = blockIdx.x * 64;

    if (z == 0) {
        const bf16* Bh = g_Wgru_h + gate * SZGRU + 512;   // h-part of layer0 W
        const bf16* Bl = g_Wgru_l + gate * SZGRU + 512;
        const float* X = (gate ? g_Xr0 : g_Xu0) + w * BH;
        mma_gemm<64>(g_h0h, g_h0l, Hh, 0, Bh, Bl, 1024, n0, Hh,
            [&] (int r, int c, float v) {
                int idx = r * Hh + c;
                float sv = sigmoidf_(v + X[idx]);
                if (gate == 0) g_u0f[idx] = sv;
                else {
                    float rh = sv * g_h0f[idx];
                    bf16 h, l; splitbf(rh, h, l);
                    g_rh0h[idx] = h; g_rh0l[idx] = l;
                }
            });
    } else {
        const bf16* Bh = g_Wgru_h + (3 + gate) * SZGRU;
        const bf16* Bl = g_Wgru_l + (3 + gate) * SZGRU;
        const float* bi = gate ? br1 : bu1;
        int par = (w - 1) & 1;
        mma_gemm<64>(g_c1h, g_c1l, 1024, 0, Bh, Bl, 1024, n0, 1024,
            [&] (int r, int c, float v) {
                int idx = r * Hh + c;
                float sv = sigmoidf_(v + bi[c]);
                if (gate == 0) g_u1f[idx] = sv;
                else {
                    float rh = sv * g_h1f[idx];
                    bf16 h, l; splitbf(rh, h, l);
                    int ci = r * 1024 + Hh + c;
                    g_c2h[par][ci] = h; g_c2l[par][ci] = l;
                }
            });
    }
}

// ---------------- wave c: z=0 layer0 cand+update @t=w ; z=1 layer1 @t=w-1 ----------------
__global__ __launch_bounds__(256, 1) void k_c(int w, const float* __restrict__ bc1)
{
    int z = blockIdx.z;
    if (z == 0 && w >= Tt) return;
    if (z == 1 && w == 0) return;
    int n0 = blockIdx.x * 64;

    if (z == 0) {
        const bf16* Bh = g_Wgru_h + 2 * SZGRU + 512;
        const bf16* Bl = g_Wgru_l + 2 * SZGRU + 512;
        const float* Xc = g_Xc0 + w * BH;
        int par = w & 1;
        mma_gemm<64>(g_rh0h, g_rh0l, Hh, 0, Bh, Bl, 1024, n0, Hh,
            [&] (int r, int c, float v) {
                int idx = r * Hh + c;
                float cand = tanhf(v + Xc[idx]);
                float u = g_u0f[idx], hv = g_h0f[idx];
                float hn = u * hv + (1.0f - u) * cand;
                g_h0f[idx] = hn;
                bf16 h, l; splitbf(hn, h, l);
                g_h0h[idx] = h; g_h0l[idx] = l;
                int ci = r * 1024 + c;
                g_c1h[ci] = h; g_c1l[ci] = l;
                g_c2h[par][ci] = h; g_c2l[par][ci] = l;
            });
    } else {
        int par = (w - 1) & 1;
        const bf16* Bh = g_Wgru_h + 5 * SZGRU;
        const bf16* Bl = g_Wgru_l + 5 * SZGRU;
        mma_gemm<64>(g_c2h[par], g_c2l[par], 1024, 0, Bh, Bl, 1024, n0, 1024,
            [&] (int r, int c, float v) {
                int idx = r * Hh + c;
                float cand = tanhf(v + bc1[c]);
                float u = g_u1f[idx], hv = g_h1f[idx];
                float hn = u * hv + (1.0f - u) * cand;
                g_h1f[idx] = hn;
                bf16 h, l; splitbf(hn, h, l);
                g_c1h[r * 1024 + Hh + c] = h;
                g_c1l[r * 1024 + Hh + c] = l;
                int xi = ((w - 1) * Bb + r) * Hh + c;
                g_X1h[xi] = h; g_X1l[xi] = l;
            });
    }
}

// ---------------- logits: [T*B, H] @ W_out[H, V] ----------------
__global__ __launch_bounds__(256, 1) void k_logits(const float* __restrict__ bout,
                                                   float* __restrict__ out)
{
    int n0 = blockIdx.x * 128, m0 = blockIdx.y * 128;
    mma_gemm<128>(g_X1h, g_X1l, Hh, m0, g_Wout_h, g_Wout_l, Hh, n0, Hh,
        [&] (int r, int c, float v) {
            if (c < Vv) {
                int t = r >> 7, b = r & 127;
                out[(long long)(b * Tt + t) * Vv + c] = v + bout[c];
            }
        });
}

// ---------------- final states into output tail ----------------
__global__ __launch_bounds__(256) void k_final(float* __restrict__ out)
{
    int i = blockIdx.x * 256 + threadIdx.x;
    int l = i >> 16;
    int j = i & (BH - 1);
    out[(long long)Bb * Tt * Vv + i] = l ? g_h1f[j] : g_h0f[j];
}

// ---------------- launch ----------------
extern "C" void kernel_launch(void* const* d_in, const int* in_sizes, int n_in,
                              void* d_out, int out_size)
{
    const float* vgg   = (const float*)d_in[0];
    const int*   xTok  = (const int*)  d_in[1];
    const float* emb   = (const float*)d_in[2];
    const float* W_in  = (const float*)d_in[3];
    const float* b_in  = (const float*)d_in[4];
    const float* Wu    = (const float*)d_in[5];
    const float* bu    = (const float*)d_in[6];
    const float* Wr    = (const float*)d_in[7];
    const float* br    = (const float*)d_in[8];
    const float* Wc    = (const float*)d_in[9];
    const float* bc    = (const float*)d_in[10];
    const float* W_out = (const float*)d_in[11];
    const float* b_out = (const float*)d_in[12];
    float* out = (float*)d_out;

    static int attr_done = 0;
    cudaFuncSetAttribute(k_init,   cudaFuncAttributeMaxDynamicSharedMemorySize, SMEM128);
    cudaFuncSetAttribute(k_xpre,   cudaFuncAttributeMaxDynamicSharedMemorySize, SMEM128);
    cudaFuncSetAttribute(k_logits, cudaFuncAttributeMaxDynamicSharedMemorySize, SMEM128);
    cudaFuncSetAttribute(k_ur,     cudaFuncAttributeMaxDynamicSharedMemorySize, SMEM64);
    cudaFuncSetAttribute(k_c,      cudaFuncAttributeMaxDynamicSharedMemorySize, SMEM64);
    (void)attr_done;

    // ---- prepack weights (transpose + bf16 split) ----
    bf16 *Wgh, *Wgl, *Wih, *Wil, *Woh, *Wol;
    cudaGetSymbolAddress((void**)&Wgh, g_Wgru_h);
    cudaGetSymbolAddress((void**)&Wgl, g_Wgru_l);
    cudaGetSymbolAddress((void**)&Wih, g_Win_h);
    cudaGetSymbolAddress((void**)&Wil, g_Win_l);
    cudaGetSymbolAddress((void**)&Woh, g_Wout_h);
    cudaGetSymbolAddress((void**)&Wol, g_Wout_l);

    pk_vgg<<<(Bb * Ff) / 256, 256>>>(vgg);
    pk_T<<<dim3(16, 128), 256>>>(W_in, Wih, Wil, Ff, Hh, Hh);
    pk_T<<<dim3(16, 32), 256>>>(Wu,            Wgh + 0*SZGRU, Wgl + 0*SZGRU, 1024, Hh, Hh);
    pk_T<<<dim3(16, 32), 256>>>(Wr,            Wgh + 1*SZGRU, Wgl + 1*SZGRU, 1024, Hh, Hh);
    pk_T<<<dim3(16, 32), 256>>>(Wc,            Wgh + 2*SZGRU, Wgl + 2*SZGRU, 1024, Hh, Hh);
    pk_T<<<dim3(16, 32), 256>>>(Wu + 1024*Hh,  Wgh + 3*SZGRU, Wgl + 3*SZGRU, 1024, Hh, Hh);
    pk_T<<<dim3(16, 32), 256>>>(Wr + 1024*Hh,  Wgh + 4*SZGRU, Wgl + 4*SZGRU, 1024, Hh, Hh);
    pk_T<<<dim3(16, 32), 256>>>(Wc + 1024*Hh,  Wgh + 5*SZGRU, Wgl + 5*SZGRU, 1024, Hh, Hh);
    pk_T<<<dim3(Vpad / 32, 16), 256>>>(W_out, Woh, Wol, Hh, Vv, Vpad);

    // ---- init + embeddings + x-projections ----
    k_init<<<4, 256, SMEM128>>>(b_in);
    k_gather<<<TBH / 256, 256>>>(emb, xTok);
    k_xpre<<<dim3(4, Tt * Bb / 128, 3), 256, SMEM128>>>(bu, br, bc);

    // ---- pipelined wavefront scan ----
    const float* bu1 = bu + Hh;
    const float* br1 = br + Hh;
    const float* bc1 = bc + Hh;
    for (int w = 0; w <= Tt; w++) {
        k_ur<<<dim3(8, 2, 2), 256, SMEM64>>>(w, bu1, br1);
        k_c <<<dim3(8, 1, 2), 256, SMEM64>>>(w, bc1);
    }

    // ---- deferred logits + final state ----
    k_logits<<<dim3(Vpad / 128, Tt * Bb / 128), 256, SMEM128>>>(b_out, out);
    k_final<<<(2 * BH) / 256, 256>>>(out);
}

// round 7
// speedup vs baseline: 4.4206x; 2.1960x over previous
#include <cuda_runtime.h>
#include <cuda_bf16.h>
#include <math.h>
#include <stdint.h>

#define Bb 128
#define Tt 30
#define Vv 10000
#define Hh 512
#define Ff 4096
#define BH (Bb*Hh)
#define TBH (Tt*Bb*Hh)
#define Vpad 10112
#define SZGRU (512*1024)

typedef __nv_bfloat16 bf16;
typedef __nv_bfloat162 bf162;

__device__ float g_h0f[BH], g_h1f[BH], g_u0f[BH], g_u1f[BH];
__device__ float g_Xu0[TBH], g_Xr0[TBH], g_Xc0[TBH];
__device__ float g_ipart[4][BH];

__device__ __align__(16) bf16 g_vgg_h[Bb*Ff], g_vgg_l[Bb*Ff];
__device__ __align__(16) bf16 g_xemb_h[TBH], g_xemb_l[TBH];
__device__ __align__(16) bf16 g_h0h[BH], g_h0l[BH];
__device__ __align__(16) bf16 g_rh0h[BH], g_rh0l[BH];
__device__ __align__(16) bf16 g_c1h[Bb*1024], g_c1l[Bb*1024];
__device__ __align__(16) bf16 g_c2h[2][Bb*1024], g_c2l[2][Bb*1024];
__device__ __align__(16) bf16 g_X1h[TBH], g_X1l[TBH];
__device__ __align__(16) bf16 g_Win_h[Hh*Ff], g_Win_l[Hh*Ff];
__device__ __align__(16) bf16 g_Wgru_h[6*SZGRU], g_Wgru_l[6*SZGRU];
__device__ __align__(16) bf16 g_Wout_h[Vpad*Hh], g_Wout_l[Vpad*Hh];

__device__ __forceinline__ uint32_t smem_u32(const void* p) {
    uint32_t a;
    asm("{ .reg .u64 t; cvta.to.shared.u64 t, %1; cvt.u32.u64 %0, t; }" : "=r"(a) : "l"(p));
    return a;
}
__device__ __forceinline__ void cpasync16(uint32_t dst, const void* src) {
    asm volatile("cp.async.cg.shared.global [%0], [%1], 16;" :: "r"(dst), "l"(src) : "memory");
}
#define CP_COMMIT() asm volatile("cp.async.commit_group;" ::: "memory")
#define CP_WAIT1()  asm volatile("cp.async.wait_group 1;" ::: "memory")
#define CP_WAIT0()  asm volatile("cp.async.wait_group 0;" ::: "memory")
#define LDSM4(R, addr) \
    asm volatile("ldmatrix.sync.aligned.m8n8.x4.shared.b16 {%0,%1,%2,%3}, [%4];" \
        : "=r"((R)[0]), "=r"((R)[1]), "=r"((R)[2]), "=r"((R)[3]) : "r"(addr))

__device__ __forceinline__ void mmaop(float* c, const uint32_t* a, const uint32_t* b) {
    asm volatile("mma.sync.aligned.m16n8k16.row.col.f32.bf16.bf16.f32 "
        "{%0,%1,%2,%3}, {%4,%5,%6,%7}, {%8,%9}, {%0,%1,%2,%3};"
        : "+f"(c[0]), "+f"(c[1]), "+f"(c[2]), "+f"(c[3])
        : "r"(a[0]), "r"(a[1]), "r"(a[2]), "r"(a[3]), "r"(b[0]), "r"(b[1]));
}
__device__ __forceinline__ float sigmoidf_(float x) { return 1.0f / (1.0f + expf(-x)); }
__device__ __forceinline__ void sp2(bf16* H, bf16* L, int i, float a, float b) {
    bf16 ha = __float2bfloat16(a), hb = __float2bfloat16(b);
    bf162 hv; hv.x = ha; hv.y = hb;
    bf162 lv; lv.x = __float2bfloat16(a - __bfloat162float(ha));
    lv.y = __float2bfloat16(b - __bfloat162float(hb));
    *(bf162*)&H[i] = hv; *(bf162*)&L[i] = lv;
}

// ---- generic split-3 bf16 mma GEMM: D[TM x TN] = A[TM,K] @ B[N,K]^T ----
// 256 thr = 8 warps (4 m x 2 n). ROWB=80 smem pitch. Epi(r, c, v0, v1) pairs.
#define ROWB 80
template<int TM, int TN, typename Epi>
__device__ __forceinline__ void mma_gemm(
    const bf16* __restrict__ Ah, const bf16* __restrict__ Al, int lda, int m0,
    const bf16* __restrict__ Bh, const bf16* __restrict__ Bl, int ldb, int n0,
    int K, Epi epi)
{
    extern __shared__ char smem[];
    constexpr int ASZ = TM * ROWB, BSZ = TN * ROWB, STG = 2*ASZ + 2*BSZ;
    constexpr int WM = TM / 4, WN = TN / 2, FM = WM / 16, NF = WN / 8;
    const uint32_t s0 = smem_u32(smem);
    const int tid = threadIdx.x, lane = tid & 31, wid = tid >> 5;
    const int wm = wid >> 1, wn = wid & 1;
    const int lrow = lane & 15, lhalf = lane >> 4;
    float acc[FM][NF][4] = {};

    auto issue = [&](int ch, int st) {
        uint32_t d = s0 + st * STG;
        int k0 = ch * 32;
        #pragma unroll
        for (int v = tid; v < TM * 4; v += 256) {
            int row = v >> 2, c = v & 3;
            cpasync16(d + row*ROWB + c*16,       Ah + (m0+row)*lda + k0 + c*8);
            cpasync16(d + ASZ + row*ROWB + c*16, Al + (m0+row)*lda + k0 + c*8);
        }
        #pragma unroll
        for (int v = tid; v < TN * 4; v += 256) {
            int row = v >> 2, c = v & 3;
            cpasync16(d + 2*ASZ + row*ROWB + c*16,       Bh + (n0+row)*ldb + k0 + c*8);
            cpasync16(d + 2*ASZ + BSZ + row*ROWB + c*16, Bl + (n0+row)*ldb + k0 + c*8);
        }
        CP_COMMIT();
    };

    const int NC = K / 32;
    issue(0, 0);
    for (int ch = 0; ch < NC; ch++) {
        int st = ch & 1;
        if (ch + 1 < NC) { issue(ch + 1, (ch + 1) & 1); CP_WAIT1(); }
        else CP_WAIT0();
        __syncthreads();
        uint32_t d = s0 + st * STG;
        #pragma unroll
        for (int kk = 0; kk < 2; kk++) {
            uint32_t ah[FM][4], al[FM][4], bh[NF][2], bl[NF][2];
            #pragma unroll
            for (int f = 0; f < FM; f++) {
                uint32_t a = d + (wm*WM + f*16 + lrow)*ROWB + lhalf*16 + kk*32;
                LDSM4(ah[f], a);
                LDSM4(al[f], a + ASZ);
            }
            #pragma unroll
            for (int g = 0; g < NF; g += 2) {
                uint32_t b = d + 2*ASZ + (wn*WN + g*8 + lrow)*ROWB + lhalf*16 + kk*32;
                uint32_t t4[4];
                LDSM4(t4, b);
                bh[g][0]=t4[0]; bh[g][1]=t4[2]; bh[g+1][0]=t4[1]; bh[g+1][1]=t4[3];
                LDSM4(t4, b + BSZ);
                bl[g][0]=t4[0]; bl[g][1]=t4[2]; bl[g+1][0]=t4[1]; bl[g+1][1]=t4[3];
            }
            #pragma unroll
            for (int f = 0; f < FM; f++)
                #pragma unroll
                for (int g = 0; g < NF; g++) {
                    mmaop(acc[f][g], ah[f], bh[g]);
                    mmaop(acc[f][g], ah[f], bl[g]);
                    mmaop(acc[f][g], al[f], bh[g]);
                }
        }
        __syncthreads();
    }
    #pragma unroll
    for (int f = 0; f < FM; f++)
        #pragma unroll
        for (int g = 0; g < NF; g++) {
            int r = m0 + wm*WM + f*16 + (lane >> 2);
            int c = n0 + wn*WN + g*8 + (lane & 3)*2;
            epi(r,     c, acc[f][g][0], acc[f][g][1]);
            epi(r + 8, c, acc[f][g][2], acc[f][g][3]);
        }
}
#define SMEM_S  (2 * (2*64*ROWB + 2*32*ROWB))     // 30720
#define SMEM_L  (2 * (2*128*ROWB + 2*64*ROWB))    // 61440

// ---- prepack ----
__global__ __launch_bounds__(256) void pk_T(const float* __restrict__ src,
                                            bf16* __restrict__ dh, bf16* __restrict__ dl,
                                            int K, int N, int Npad)
{
    __shared__ float tile[32][33];
    int kb = blockIdx.y * 32, nb = blockIdx.x * 32;
    int tx = threadIdx.x & 31, ty = threadIdx.x >> 5;
    for (int i = ty; i < 32; i += 8) {
        int n = nb + tx;
        tile[i][tx] = (n < N) ? src[(kb + i) * N + n] : 0.f;
    }
    __syncthreads();
    for (int i = ty; i < 32; i += 8) {
        int n = nb + i, k = kb + tx;
        if (n < Npad) {
            float x = tile[tx][i];
            bf16 h = __float2bfloat16(x);
            dh[n * K + k] = h;
            dl[n * K + k] = __float2bfloat16(x - __bfloat162float(h));
        }
    }
}
__global__ __launch_bounds__(256) void pk_vgg(const float* __restrict__ src)
{
    int i = (blockIdx.x * 256 + threadIdx.x) * 2;
    sp2(g_vgg_h, g_vgg_l, i, src[i], src[i + 1]);
}
__global__ __launch_bounds__(256) void k_gather(const float* __restrict__ emb,
                                                const int* __restrict__ tok)
{
    int idx = (blockIdx.x * 256 + threadIdx.x) * 2;
    int r = idx >> 9, e = idx & 511;
    int token = tok[(r & 127) * Tt + (r >> 7)];
    sp2(g_xemb_h, g_xemb_l, idx, emb[token * Hh + e], emb[token * Hh + e + 1]);
}

// ---- init: split-K partials then finalize ----
__global__ __launch_bounds__(256, 1) void k_initp()
{
    int cta = blockIdx.x;                 // 128 = ks4 x mt2 x nt16
    int ks = cta >> 5, mt = (cta >> 4) & 1, nt = cta & 15;
    int koff = ks * 1024;
    float* out = g_ipart[ks];
    mma_gemm<64,32>(g_vgg_h + koff, g_vgg_l + koff, Ff, mt*64,
                    g_Win_h + koff, g_Win_l + koff, Ff, nt*32, 1024,
        [&](int r, int c, float v0, float v1) {
            out[r*Hh + c] = v0; out[r*Hh + c + 1] = v1;
        });
}
__global__ __launch_bounds__(256) void k_initf(const float* __restrict__ b_in)
{
    int i = blockIdx.x * 256 + threadIdx.x;
    float v = tanhf(g_ipart[0][i] + g_ipart[1][i] + g_ipart[2][i] + g_ipart[3][i]
                    + b_in[i & 511]);
    g_h0f[i] = v; g_h1f[i] = v;
    bf16 h = __float2bfloat16(v);
    bf16 l = __float2bfloat16(v - __bfloat162float(h));
    g_h0h[i] = h; g_h0l[i] = l;
    int ci = (i >> 9) * 1024 + 512 + (i & 511);
    g_c1h[ci] = h; g_c1l[ci] = l;
}

// ---- layer0 x-projections for all t ----
__global__ __launch_bounds__(256, 1) void k_xpre(const float* __restrict__ bu,
                                                 const float* __restrict__ br,
                                                 const float* __restrict__ bc)
{
    int n0 = blockIdx.x * 64, m0 = blockIdx.y * 128, gate = blockIdx.z;
    const float* bi = (gate == 0) ? bu : (gate == 1) ? br : bc;
    float* out = (gate == 0) ? g_Xu0 : (gate == 1) ? g_Xr0 : g_Xc0;
    mma_gemm<128,64>(g_xemb_h, g_xemb_l, Hh, m0,
                     g_Wgru_h + gate*SZGRU, g_Wgru_l + gate*SZGRU, 1024, n0, Hh,
        [&](int r, int c, float v0, float v1) {
            float2 val = make_float2(v0 + bi[c], v1 + bi[c + 1]);
            *(float2*)&out[r*Hh + c] = val;
        });
}

// ---- wave UR: z={0,1}: layer0 u/r @t=w ; z={2,3}: layer1 u/r @t=w-1 ----
__global__ __launch_bounds__(256, 1) void k_ur(int w,
                                               const float* __restrict__ bu1,
                                               const float* __restrict__ br1)
{
    int nt = blockIdx.x, mt = blockIdx.y, z = blockIdx.z;
    int n0 = nt * 32;
    if (z < 2) {
        if (w >= Tt) return;
        int gate = z;
        const float* X = (gate ? g_Xr0 : g_Xu0) + w * BH;
        mma_gemm<64,32>(g_h0h, g_h0l, Hh, mt*64,
            g_Wgru_h + gate*SZGRU + 512, g_Wgru_l + gate*SZGRU + 512,
            1024, n0, Hh,
            [&](int r, int c, float v0, float v1) {
                int idx = r*Hh + c;
                float s0 = sigmoidf_(v0 + X[idx]);
                float s1 = sigmoidf_(v1 + X[idx+1]);
                if (gate == 0) { g_u0f[idx] = s0; g_u0f[idx+1] = s1; }
                else sp2(g_rh0h, g_rh0l, idx, s0*g_h0f[idx], s1*g_h0f[idx+1]);
            });
    } else {
        if (w == 0) return;
        int gate = z - 2, par = (w - 1) & 1;
        const float* bi = gate ? br1 : bu1;
        mma_gemm<64,32>(g_c1h, g_c1l, 1024, mt*64,
            g_Wgru_h + (3+gate)*SZGRU, g_Wgru_l + (3+gate)*SZGRU,
            1024, n0, 1024,
            [&](int r, int c, float v0, float v1) {
                int idx = r*Hh + c;
                float s0 = sigmoidf_(v0 + bi[c]);
                float s1 = sigmoidf_(v1 + bi[c+1]);
                if (gate == 0) { g_u1f[idx] = s0; g_u1f[idx+1] = s1; }
                else sp2(g_c2h[par], g_c2l[par], r*1024 + 512 + c,
                         s0*g_h1f[idx], s1*g_h1f[idx+1]);
            });
    }
}

// ---- wave C: z=0: layer0 cand+update @t=w ; z=1: layer1 @t=w-1 ----
__global__ __launch_bounds__(256, 1) void k_c(int w, const float* __restrict__ bc1)
{
    int nt = blockIdx.x, mt = blockIdx.y, z = blockIdx.z;
    int n0 = nt * 32;
    if (z == 0) {
        if (w >= Tt) return;
        int par = w & 1;
        const float* Xc = g_Xc0 + w * BH;
        mma_gemm<64,32>(g_rh0h, g_rh0l, Hh, mt*64,
            g_Wgru_h + 2*SZGRU + 512, g_Wgru_l + 2*SZGRU + 512,
            1024, n0, Hh,
            [&](int r, int c, float v0, float v1) {
                int idx = r*Hh + c;
                float c0 = tanhf(v0 + Xc[idx]), c1 = tanhf(v1 + Xc[idx+1]);
                float u0 = g_u0f[idx], u1 = g_u0f[idx+1];
                float h0 = u0*g_h0f[idx]   + (1.f-u0)*c0;
                float h1 = u1*g_h0f[idx+1] + (1.f-u1)*c1;
                g_h0f[idx] = h0; g_h0f[idx+1] = h1;
                sp2(g_h0h, g_h0l, idx, h0, h1);
                int ci = r*1024 + c;
                sp2(g_c1h, g_c1l, ci, h0, h1);
                sp2(g_c2h[par], g_c2l[par], ci, h0, h1);
            });
    } else {
        if (w == 0) return;
        int par = (w - 1) & 1;
        mma_gemm<64,32>(g_c2h[par], g_c2l[par], 1024, mt*64,
            g_Wgru_h + 5*SZGRU, g_Wgru_l + 5*SZGRU, 1024, n0, 1024,
            [&](int r, int c, float v0, float v1) {
                int idx = r*Hh + c;
                float c0 = tanhf(v0 + bc1[c]), c1 = tanhf(v1 + bc1[c+1]);
                float u0 = g_u1f[idx], u1 = g_u1f[idx+1];
                float h0 = u0*g_h1f[idx]   + (1.f-u0)*c0;
                float h1 = u1*g_h1f[idx+1] + (1.f-u1)*c1;
                g_h1f[idx] = h0; g_h1f[idx+1] = h1;
                sp2(g_c1h, g_c1l, r*1024 + 512 + c, h0, h1);
                sp2(g_X1h, g_X1l, ((w-1)*Bb + r)*Hh + c, h0, h1);
            });
    }
}

// ---- logits ----
__global__ __launch_bounds__(256, 1) void k_logits(const float* __restrict__ bout,
                                                   float* __restrict__ out)
{
    int n0 = blockIdx.x * 64, m0 = blockIdx.y * 128;
    mma_gemm<128,64>(g_X1h, g_X1l, Hh, m0, g_Wout_h, g_Wout_l, Hh, n0, Hh,
        [&](int r, int c, float v0, float v1) {
            if (c < Vv) {
                int t = r >> 7, b = r & 127;
                long long base = (long long)(b * Tt + t) * Vv;
                out[base + c] = v0 + bout[c];
                if (c + 1 < Vv) out[base + c + 1] = v1 + bout[c + 1];
            }
        });
}

__global__ __launch_bounds__(256) void k_final(float* __restrict__ out)
{
    int i = blockIdx.x * 256 + threadIdx.x;
    out[(long long)Bb * Tt * Vv + i] = (i >> 16) ? g_h1f[i & (BH-1)] : g_h0f[i & (BH-1)];
}

// ---- launch ----
extern "C" void kernel_launch(void* const* d_in, const int* in_sizes, int n_in,
                              void* d_out, int out_size)
{
    const float* vgg   = (const float*)d_in[0];
    const int*   xTok  = (const int*)  d_in[1];
    const float* emb   = (const float*)d_in[2];
    const float* W_in  = (const float*)d_in[3];
    const float* b_in  = (const float*)d_in[4];
    const float* Wu    = (const float*)d_in[5];
    const float* bu    = (const float*)d_in[6];
    const float* Wr    = (const float*)d_in[7];
    const float* br    = (const float*)d_in[8];
    const float* Wc    = (const float*)d_in[9];
    const float* bc    = (const float*)d_in[10];
    const float* W_out = (const float*)d_in[11];
    const float* b_out = (const float*)d_in[12];
    float* out = (float*)d_out;

    cudaFuncSetAttribute(k_xpre,   cudaFuncAttributeMaxDynamicSharedMemorySize, SMEM_L);
    cudaFuncSetAttribute(k_logits, cudaFuncAttributeMaxDynamicSharedMemorySize, SMEM_L);

    bf16 *Wgh, *Wgl, *Wih, *Wil, *Woh, *Wol;
    cudaGetSymbolAddress((void**)&Wgh, g_Wgru_h);
    cudaGetSymbolAddress((void**)&Wgl, g_Wgru_l);
    cudaGetSymbolAddress((void**)&Wih, g_Win_h);
    cudaGetSymbolAddress((void**)&Wil, g_Win_l);
    cudaGetSymbolAddress((void**)&Woh, g_Wout_h);
    cudaGetSymbolAddress((void**)&Wol, g_Wout_l);

    pk_vgg<<<(Bb*Ff/2)/256, 256>>>(vgg);
    pk_T<<<dim3(16, 128), 256>>>(W_in, Wih, Wil, Ff, Hh, Hh);
    pk_T<<<dim3(16, 32), 256>>>(Wu,           Wgh + 0*SZGRU, Wgl + 0*SZGRU, 1024, Hh, Hh);
    pk_T<<<dim3(16, 32), 256>>>(Wr,           Wgh + 1*SZGRU, Wgl + 1*SZGRU, 1024, Hh, Hh);
    pk_T<<<dim3(16, 32), 256>>>(Wc,           Wgh + 2*SZGRU, Wgl + 2*SZGRU, 1024, Hh, Hh);
    pk_T<<<dim3(16, 32), 256>>>(Wu + 1024*Hh, Wgh + 3*SZGRU, Wgl + 3*SZGRU, 1024, Hh, Hh);
    pk_T<<<dim3(16, 32), 256>>>(Wr + 1024*Hh, Wgh + 4*SZGRU, Wgl + 4*SZGRU, 1024, Hh, Hh);
    pk_T<<<dim3(16, 32), 256>>>(Wc + 1024*Hh, Wgh + 5*SZGRU, Wgl + 5*SZGRU, 1024, Hh, Hh);
    pk_T<<<dim3(Vpad/32, 16), 256>>>(W_out, Woh, Wol, Hh, Vv, Vpad);

    k_initp<<<128, 256, SMEM_S>>>();
    k_initf<<<BH/256, 256>>>(b_in);
    k_gather<<<(TBH/2)/256, 256>>>(emb, xTok);
    k_xpre<<<dim3(8, Tt*Bb/128, 3), 256, SMEM_L>>>(bu, br, bc);

    for (int w = 0; w <= Tt; w++) {
        k_ur<<<dim3(16, 2, 4), 256, SMEM_S>>>(w, bu + Hh, br + Hh);
        k_c <<<dim3(16, 2, 2), 256, SMEM_S>>>(w, bc + Hh);
    }

    k_logits<<<dim3(Vpad/64, Tt*Bb/128), 256, SMEM_L>>>(b_out, out);
    k_final<<<(2*BH)/256, 256>>>(out);
}

// round 8
// speedup vs baseline: 4.5829x; 1.0367x over previous
#include <cuda_runtime.h>
#include <cuda_bf16.h>
#include <math.h>
#include <stdint.h>

#define Bb 128
#define Tt 30
#define Vv 10000
#define Hh 512
#define Ff 4096
#define BH (Bb*Hh)
#define TBH (Tt*Bb*Hh)
#define Vpad 10112
#define SZGRU (512*1024)

typedef __nv_bfloat16 bf16;
typedef __nv_bfloat162 bf162;

__device__ float g_h0f[BH], g_h1f[BH], g_u0f[BH], g_u1f[BH];
__device__ float g_Xu0[TBH], g_Xr0[TBH], g_Xc0[TBH];
__device__ float g_ipart[4][BH];

__device__ __align__(16) bf16 g_vgg_h[Bb*Ff], g_vgg_l[Bb*Ff];
__device__ __align__(16) bf16 g_xemb_h[TBH], g_xemb_l[TBH];
__device__ __align__(16) bf16 g_h0h[BH], g_h0l[BH];
__device__ __align__(16) bf16 g_rh0h[BH], g_rh0l[BH];
__device__ __align__(16) bf16 g_c1h[Bb*1024], g_c1l[Bb*1024];
__device__ __align__(16) bf16 g_c2h[2][Bb*1024], g_c2l[2][Bb*1024];
__device__ __align__(16) bf16 g_X1h[TBH], g_X1l[TBH];
__device__ __align__(16) bf16 g_Win_h[Hh*Ff], g_Win_l[Hh*Ff];
__device__ __align__(16) bf16 g_Wgru_h[6*SZGRU], g_Wgru_l[6*SZGRU];
__device__ __align__(16) bf16 g_Wout_h[Vpad*Hh], g_Wout_l[Vpad*Hh];

__device__ __forceinline__ uint32_t smem_u32(const void* p) {
    uint32_t a;
    asm("{ .reg .u64 t; cvta.to.shared.u64 t, %1; cvt.u32.u64 %0, t; }" : "=r"(a) : "l"(p));
    return a;
}
__device__ __forceinline__ void cpasync16(uint32_t dst, const void* src) {
    asm volatile("cp.async.cg.shared.global [%0], [%1], 16;" :: "r"(dst), "l"(src) : "memory");
}
#define CP_COMMIT() asm volatile("cp.async.commit_group;" ::: "memory")
#define CP_WAIT1()  asm volatile("cp.async.wait_group 1;" ::: "memory")
#define CP_WAIT0()  asm volatile("cp.async.wait_group 0;" ::: "memory")
#define LDSM4(R, addr) \
    asm volatile("ldmatrix.sync.aligned.m8n8.x4.shared.b16 {%0,%1,%2,%3}, [%4];" \
        : "=r"((R)[0]), "=r"((R)[1]), "=r"((R)[2]), "=r"((R)[3]) : "r"(addr))

__device__ __forceinline__ void mmaop(float* c, const uint32_t* a, const uint32_t* b) {
    asm volatile("mma.sync.aligned.m16n8k16.row.col.f32.bf16.bf16.f32 "
        "{%0,%1,%2,%3}, {%4,%5,%6,%7}, {%8,%9}, {%0,%1,%2,%3};"
        : "+f"(c[0]), "+f"(c[1]), "+f"(c[2]), "+f"(c[3])
        : "r"(a[0]), "r"(a[1]), "r"(a[2]), "r"(a[3]), "r"(b[0]), "r"(b[1]));
}
__device__ __forceinline__ float sigmoidf_(float x) { return 1.0f / (1.0f + expf(-x)); }
__device__ __forceinline__ void sp2(bf16* H, bf16* L, int i, float a, float b) {
    bf16 ha = __float2bfloat16(a), hb = __float2bfloat16(b);
    bf162 hv; hv.x = ha; hv.y = hb;
    bf162 lv; lv.x = __float2bfloat16(a - __bfloat162float(ha));
    lv.y = __float2bfloat16(b - __bfloat162float(hb));
    *(bf162*)&H[i] = hv; *(bf162*)&L[i] = lv;
}

// ---- generic split-3 bf16 mma GEMM: D[TM x TN] = A[TM,K] @ B[N,K]^T ----
// 256 thr = 8 warps (4 m x 2 n). ROWB=80 smem pitch. B-frags processed in
// groups of <=4 to bound live registers. Epi(r, c, v0, v1) receives col pairs.
#define ROWB 80
template<int TM, int TN, typename Epi>
__device__ __forceinline__ void mma_gemm(
    const bf16* __restrict__ Ah, const bf16* __restrict__ Al, int lda, int m0,
    const bf16* __restrict__ Bh, const bf16* __restrict__ Bl, int ldb, int n0,
    int K, Epi epi)
{
    extern __shared__ char smem[];
    constexpr int ASZ = TM * ROWB, BSZ = TN * ROWB, STG = 2*ASZ + 2*BSZ;
    constexpr int WM = TM / 4, WN = TN / 2, FM = WM / 16, NF = WN / 8;
    constexpr int GG = (NF > 4) ? 4 : NF;
    const uint32_t s0 = smem_u32(smem);
    const int tid = threadIdx.x, lane = tid & 31, wid = tid >> 5;
    const int wm = wid >> 1, wn = wid & 1;
    const int lrow = lane & 15, lhalf = lane >> 4;
    float acc[FM][NF][4] = {};

    auto issue = [&](int ch, int st) {
        uint32_t d = s0 + st * STG;
        int k0 = ch * 32;
        #pragma unroll
        for (int v = tid; v < TM * 4; v += 256) {
            int row = v >> 2, c = v & 3;
            cpasync16(d + row*ROWB + c*16,       Ah + (m0+row)*lda + k0 + c*8);
            cpasync16(d + ASZ + row*ROWB + c*16, Al + (m0+row)*lda + k0 + c*8);
        }
        #pragma unroll
        for (int v = tid; v < TN * 4; v += 256) {
            int row = v >> 2, c = v & 3;
            cpasync16(d + 2*ASZ + row*ROWB + c*16,       Bh + (n0+row)*ldb + k0 + c*8);
            cpasync16(d + 2*ASZ + BSZ + row*ROWB + c*16, Bl + (n0+row)*ldb + k0 + c*8);
        }
        CP_COMMIT();
    };

    const int NC = K / 32;
    issue(0, 0);
    for (int ch = 0; ch < NC; ch++) {
        int st = ch & 1;
        if (ch + 1 < NC) { issue(ch + 1, (ch + 1) & 1); CP_WAIT1(); }
        else CP_WAIT0();
        __syncthreads();
        uint32_t d = s0 + st * STG;
        #pragma unroll
        for (int kk = 0; kk < 2; kk++) {
            uint32_t ah[FM][4], al[FM][4];
            #pragma unroll
            for (int f = 0; f < FM; f++) {
                uint32_t a = d + (wm*WM + f*16 + lrow)*ROWB + lhalf*16 + kk*32;
                LDSM4(ah[f], a);
                LDSM4(al[f], a + ASZ);
            }
            #pragma unroll
            for (int gg = 0; gg < NF; gg += GG) {
                uint32_t bh[GG][2], bl[GG][2];
                #pragma unroll
                for (int g2 = 0; g2 < GG; g2 += 2) {
                    int g = gg + g2;
                    uint32_t b = d + 2*ASZ + (wn*WN + g*8 + lrow)*ROWB + lhalf*16 + kk*32;
                    uint32_t t4[4];
                    LDSM4(t4, b);
                    bh[g2][0]=t4[0]; bh[g2][1]=t4[2]; bh[g2+1][0]=t4[1]; bh[g2+1][1]=t4[3];
                    LDSM4(t4, b + BSZ);
                    bl[g2][0]=t4[0]; bl[g2][1]=t4[2]; bl[g2+1][0]=t4[1]; bl[g2+1][1]=t4[3];
                }
                #pragma unroll
                for (int f = 0; f < FM; f++)
                    #pragma unroll
                    for (int g2 = 0; g2 < GG; g2++) {
                        mmaop(acc[f][gg+g2], ah[f], bh[g2]);
                        mmaop(acc[f][gg+g2], ah[f], bl[g2]);
                        mmaop(acc[f][gg+g2], al[f], bh[g2]);
                    }
            }
        }
        __syncthreads();
    }
    #pragma unroll
    for (int f = 0; f < FM; f++)
        #pragma unroll
        for (int g = 0; g < NF; g++) {
            int r = m0 + wm*WM + f*16 + (lane >> 2);
            int c = n0 + wn*WN + g*8 + (lane & 3)*2;
            epi(r,     c, acc[f][g][0], acc[f][g][1]);
            epi(r + 8, c, acc[f][g][2], acc[f][g][3]);
        }
}
#define SMEM_S  (2 * (2*64*ROWB + 2*32*ROWB))      // 30720
#define SMEM_X  (2 * (2*128*ROWB + 2*128*ROWB))    // 81920

// ---- prepack ----
__device__ __forceinline__ void pk_T_body(const float* __restrict__ src,
                                          bf16* __restrict__ dh, bf16* __restrict__ dl,
                                          int K, int N, int Npad, int kb, int nb)
{
    __shared__ float tile[32][33];
    int tx = threadIdx.x & 31, ty = threadIdx.x >> 5;
    for (int i = ty; i < 32; i += 8) {
        int n = nb + tx;
        tile[i][tx] = (n < N) ? src[(kb + i) * N + n] : 0.f;
    }
    __syncthreads();
    for (int i = ty; i < 32; i += 8) {
        int n = nb + i, k = kb + tx;
        if (n < Npad) {
            float x = tile[tx][i];
            bf16 h = __float2bfloat16(x);
            dh[n * K + k] = h;
            dl[n * K + k] = __float2bfloat16(x - __bfloat162float(h));
        }
    }
}
__global__ __launch_bounds__(256) void pk_T(const float* __restrict__ src,
                                            bf16* __restrict__ dh, bf16* __restrict__ dl,
                                            int K, int N, int Npad)
{
    pk_T_body(src, dh, dl, K, N, Npad, blockIdx.y * 32, blockIdx.x * 32);
}
__global__ __launch_bounds__(256) void pk_gru(const float* __restrict__ Wu,
                                              const float* __restrict__ Wr,
                                              const float* __restrict__ Wc,
                                              bf16* __restrict__ Wgh,
                                              bf16* __restrict__ Wgl)
{
    int z = blockIdx.z;                      // {u0,r0,c0,u1,r1,c1}
    int gate = (z < 3) ? z : z - 3, layer = z / 3;
    const float* src = ((gate == 0) ? Wu : (gate == 1) ? Wr : Wc) + layer * 1024 * Hh;
    pk_T_body(src, Wgh + z*SZGRU, Wgl + z*SZGRU, 1024, Hh, Hh,
              blockIdx.y * 32, blockIdx.x * 32);
}
__global__ __launch_bounds__(256) void pk_vgg(const float* __restrict__ src)
{
    int i = (blockIdx.x * 256 + threadIdx.x) * 2;
    sp2(g_vgg_h, g_vgg_l, i, src[i], src[i + 1]);
}
__global__ __launch_bounds__(256) void k_gather(const float* __restrict__ emb,
                                                const int* __restrict__ tok)
{
    int idx = (blockIdx.x * 256 + threadIdx.x) * 2;
    int r = idx >> 9, e = idx & 511;
    int token = tok[(r & 127) * Tt + (r >> 7)];
    sp2(g_xemb_h, g_xemb_l, idx, emb[token * Hh + e], emb[token * Hh + e + 1]);
}

// ---- init: split-K partials then finalize ----
__global__ __launch_bounds__(256, 1) void k_initp()
{
    int cta = blockIdx.x;                 // 128 = ks4 x mt2 x nt16
    int ks = cta >> 5, mt = (cta >> 4) & 1, nt = cta & 15;
    int koff = ks * 1024;
    float* out = g_ipart[ks];
    mma_gemm<64,32>(g_vgg_h + koff, g_vgg_l + koff, Ff, mt*64,
                    g_Win_h + koff, g_Win_l + koff, Ff, nt*32, 1024,
        [&](int r, int c, float v0, float v1) {
            out[r*Hh + c] = v0; out[r*Hh + c + 1] = v1;
        });
}
__global__ __launch_bounds__(256) void k_initf(const float* __restrict__ b_in)
{
    int i = blockIdx.x * 256 + threadIdx.x;
    float v = tanhf(g_ipart[0][i] + g_ipart[1][i] + g_ipart[2][i] + g_ipart[3][i]
                    + b_in[i & 511]);
    g_h0f[i] = v; g_h1f[i] = v;
    bf16 h = __float2bfloat16(v);
    bf16 l = __float2bfloat16(v - __bfloat162float(h));
    g_h0h[i] = h; g_h0l[i] = l;
    int ci = (i >> 9) * 1024 + 512 + (i & 511);
    g_c1h[ci] = h; g_c1l[ci] = l;
}

// ---- layer0 x-projections for all t (128x128 tiles) ----
__global__ __launch_bounds__(256, 2) void k_xpre(const float* __restrict__ bu,
                                                 const float* __restrict__ br,
                                                 const float* __restrict__ bc)
{
    int n0 = blockIdx.x * 128, m0 = blockIdx.y * 128, gate = blockIdx.z;
    const float* bi = (gate == 0) ? bu : (gate == 1) ? br : bc;
    float* out = (gate == 0) ? g_Xu0 : (gate == 1) ? g_Xr0 : g_Xc0;
    mma_gemm<128,128>(g_xemb_h, g_xemb_l, Hh, m0,
                      g_Wgru_h + gate*SZGRU, g_Wgru_l + gate*SZGRU, 1024, n0, Hh,
        [&](int r, int c, float v0, float v1) {
            float2 val = make_float2(v0 + bi[c], v1 + bi[c + 1]);
            *(float2*)&out[r*Hh + c] = val;
        });
}

// ---- wave UR: z={0,1}: layer0 u/r @t=w ; z={2,3}: layer1 u/r @t=w-1 ----
__global__ __launch_bounds__(256, 1) void k_ur(int w,
                                               const float* __restrict__ bu1,
                                               const float* __restrict__ br1)
{
    int nt = blockIdx.x, mt = blockIdx.y, z = blockIdx.z;
    int n0 = nt * 32;
    if (z < 2) {
        if (w >= Tt) return;
        int gate = z;
        const float* X = (gate ? g_Xr0 : g_Xu0) + w * BH;
        mma_gemm<64,32>(g_h0h, g_h0l, Hh, mt*64,
            g_Wgru_h + gate*SZGRU + 512, g_Wgru_l + gate*SZGRU + 512,
            1024, n0, Hh,
            [&](int r, int c, float v0, float v1) {
                int idx = r*Hh + c;
                float s0 = sigmoidf_(v0 + X[idx]);
                float s1 = sigmoidf_(v1 + X[idx+1]);
                if (gate == 0) { g_u0f[idx] = s0; g_u0f[idx+1] = s1; }
                else sp2(g_rh0h, g_rh0l, idx, s0*g_h0f[idx], s1*g_h0f[idx+1]);
            });
    } else {
        if (w == 0) return;
        int gate = z - 2, par = (w - 1) & 1;
        const float* bi = gate ? br1 : bu1;
        mma_gemm<64,32>(g_c1h, g_c1l, 1024, mt*64,
            g_Wgru_h + (3+gate)*SZGRU, g_Wgru_l + (3+gate)*SZGRU,
            1024, n0, 1024,
            [&](int r, int c, float v0, float v1) {
                int idx = r*Hh + c;
                float s0 = sigmoidf_(v0 + bi[c]);
                float s1 = sigmoidf_(v1 + bi[c+1]);
                if (gate == 0) { g_u1f[idx] = s0; g_u1f[idx+1] = s1; }
                else sp2(g_c2h[par], g_c2l[par], r*1024 + 512 + c,
                         s0*g_h1f[idx], s1*g_h1f[idx+1]);
            });
    }
}

// ---- wave C: z=0: layer0 cand+update @t=w ; z=1: layer1 @t=w-1 ----
__global__ __launch_bounds__(256, 1) void k_c(int w, const float* __restrict__ bc1)
{
    int nt = blockIdx.x, mt = blockIdx.y, z = blockIdx.z;
    int n0 = nt * 32;
    if (z == 0) {
        if (w >= Tt) return;
        int par = w & 1;
        const float* Xc = g_Xc0 + w * BH;
        mma_gemm<64,32>(g_rh0h, g_rh0l, Hh, mt*64,
            g_Wgru_h + 2*SZGRU + 512, g_Wgru_l + 2*SZGRU + 512,
            1024, n0, Hh,
            [&](int r, int c, float v0, float v1) {
                int idx = r*Hh + c;
                float c0 = tanhf(v0 + Xc[idx]), c1 = tanhf(v1 + Xc[idx+1]);
                float u0 = g_u0f[idx], u1 = g_u0f[idx+1];
                float h0 = u0*g_h0f[idx]   + (1.f-u0)*c0;
                float h1 = u1*g_h0f[idx+1] + (1.f-u1)*c1;
                g_h0f[idx] = h0; g_h0f[idx+1] = h1;
                sp2(g_h0h, g_h0l, idx, h0, h1);
                int ci = r*1024 + c;
                sp2(g_c1h, g_c1l, ci, h0, h1);
                sp2(g_c2h[par], g_c2l[par], ci, h0, h1);
            });
    } else {
        if (w == 0) return;
        int par = (w - 1) & 1;
        mma_gemm<64,32>(g_c2h[par], g_c2l[par], 1024, mt*64,
            g_Wgru_h + 5*SZGRU, g_Wgru_l + 5*SZGRU, 1024, n0, 1024,
            [&](int r, int c, float v0, float v1) {
                int idx = r*Hh + c;
                float c0 = tanhf(v0 + bc1[c]), c1 = tanhf(v1 + bc1[c+1]);
                float u0 = g_u1f[idx], u1 = g_u1f[idx+1];
                float h0 = u0*g_h1f[idx]   + (1.f-u0)*c0;
                float h1 = u1*g_h1f[idx+1] + (1.f-u1)*c1;
                g_h1f[idx] = h0; g_h1f[idx+1] = h1;
                sp2(g_c1h, g_c1l, r*1024 + 512 + c, h0, h1);
                sp2(g_X1h, g_X1l, ((w-1)*Bb + r)*Hh + c, h0, h1);
            });
    }
}

// ---- logits (128x128 tiles) ----
__global__ __launch_bounds__(256, 2) void k_logits(const float* __restrict__ bout,
                                                   float* __restrict__ out)
{
    int n0 = blockIdx.x * 128, m0 = blockIdx.y * 128;
    mma_gemm<128,128>(g_X1h, g_X1l, Hh, m0, g_Wout_h, g_Wout_l, Hh, n0, Hh,
        [&](int r, int c, float v0, float v1) {
            if (c < Vv) {
                int t = r >> 7, b = r & 127;
                long long base = (long long)(b * Tt + t) * Vv;
                out[base + c] = v0 + bout[c];
                if (c + 1 < Vv) out[base + c + 1] = v1 + bout[c + 1];
            }
        });
}

__global__ __launch_bounds__(256) void k_final(float* __restrict__ out)
{
    int i = blockIdx.x * 256 + threadIdx.x;
    out[(long long)Bb * Tt * Vv + i] = (i >> 16) ? g_h1f[i & (BH-1)] : g_h0f[i & (BH-1)];
}

// ---- launch ----
extern "C" void kernel_launch(void* const* d_in, const int* in_sizes, int n_in,
                              void* d_out, int out_size)
{
    const float* vgg   = (const float*)d_in[0];
    const int*   xTok  = (const int*)  d_in[1];
    const float* emb   = (const float*)d_in[2];
    const float* W_in  = (const float*)d_in[3];
    const float* b_in  = (const float*)d_in[4];
    const float* Wu    = (const float*)d_in[5];
    const float* bu    = (const float*)d_in[6];
    const float* Wr    = (const float*)d_in[7];
    const float* br    = (const float*)d_in[8];
    const float* Wc    = (const float*)d_in[9];
    const float* bc    = (const float*)d_in[10];
    const float* W_out = (const float*)d_in[11];
    const float* b_out = (const float*)d_in[12];
    float* out = (float*)d_out;

    cudaFuncSetAttribute(k_xpre,   cudaFuncAttributeMaxDynamicSharedMemorySize, SMEM_X);
    cudaFuncSetAttribute(k_logits, cudaFuncAttributeMaxDynamicSharedMemorySize, SMEM_X);

    bf16 *Wgh, *Wgl, *Wih, *Wil, *Woh, *Wol;
    cudaGetSymbolAddress((void**)&Wgh, g_Wgru_h);
    cudaGetSymbolAddress((void**)&Wgl, g_Wgru_l);
    cudaGetSymbolAddress((void**)&Wih, g_Win_h);
    cudaGetSymbolAddress((void**)&Wil, g_Win_l);
    cudaGetSymbolAddress((void**)&Woh, g_Wout_h);
    cudaGetSymbolAddress((void**)&Wol, g_Wout_l);

    pk_vgg<<<(Bb*Ff/2)/256, 256>>>(vgg);
    pk_T<<<dim3(16, 128), 256>>>(W_in, Wih, Wil, Ff, Hh, Hh);
    pk_gru<<<dim3(16, 32, 6), 256>>>(Wu, Wr, Wc, Wgh, Wgl);
    pk_T<<<dim3(Vpad/32, 16), 256>>>(W_out, Woh, Wol, Hh, Vv, Vpad);

    k_initp<<<128, 256, SMEM_S>>>();
    k_initf<<<BH/256, 256>>>(b_in);
    k_gather<<<(TBH/2)/256, 256>>>(emb, xTok);
    k_xpre<<<dim3(4, Tt*Bb/128, 3), 256, SMEM_X>>>(bu, br, bc);

    for (int w = 0; w <= Tt; w++) {
        k_ur<<<dim3(16, 2, 4), 256, SMEM_S>>>(w, bu + Hh, br + Hh);
        k_c <<<dim3(16, 2, 2), 256, SMEM_S>>>(w, bc + Hh);
    }

    k_logits<<<dim3(Vpad/128, Tt*Bb/128), 256, SMEM_X>>>(b_out, out);
    k_final<<<(2*BH)/256, 256>>>(out);
}

// round 9
// speedup vs baseline: 4.9336x; 1.0765x over previous
#include <cuda_runtime.h>
#include <cuda_bf16.h>
#include <cuda_fp16.h>
#include <math.h>
#include <stdint.h>

#define Bb 128
#define Tt 30
#define Vv 10000
#define Hh 512
#define Ff 4096
#define BH (Bb*Hh)
#define TBH (Tt*Bb*Hh)
#define Vpad 10112
#define SZGRU (512*1024)

typedef __nv_bfloat16 bf16;
typedef __nv_bfloat162 bf162;

__device__ float g_h0f[BH], g_h1f[BH], g_u0f[BH], g_u1f[BH];
__device__ float g_Xu0[TBH], g_Xr0[TBH], g_Xc0[TBH];
__device__ float g_ipart[4][BH];

__device__ __align__(16) bf16 g_vgg_h[Bb*Ff], g_vgg_l[Bb*Ff];
__device__ __align__(16) bf16 g_xemb_h[TBH], g_xemb_l[TBH];
__device__ __align__(16) bf16 g_h0h[BH], g_h0l[BH];
__device__ __align__(16) bf16 g_rh0h[BH], g_rh0l[BH];
__device__ __align__(16) bf16 g_c1h[Bb*1024], g_c1l[Bb*1024];
__device__ __align__(16) bf16 g_c2h[2][Bb*1024], g_c2l[2][Bb*1024];
__device__ __align__(16) __half g_X1ah[TBH], g_X1al[TBH];   // fp16 hi/lo X1
__device__ __align__(16) bf16 g_Win_h[Hh*Ff], g_Win_l[Hh*Ff];
__device__ __align__(16) bf16 g_Wgru_h[6*SZGRU], g_Wgru_l[6*SZGRU];
__device__ __align__(16) __half g_WoH[Vpad*Hh];             // fp16 W_out [N,K]

__device__ __forceinline__ uint32_t smem_u32(const void* p) {
    uint32_t a;
    asm("{ .reg .u64 t; cvta.to.shared.u64 t, %1; cvt.u32.u64 %0, t; }" : "=r"(a) : "l"(p));
    return a;
}
__device__ __forceinline__ void cpasync16(uint32_t dst, const void* src) {
    asm volatile("cp.async.cg.shared.global [%0], [%1], 16;" :: "r"(dst), "l"(src) : "memory");
}
#define CP_COMMIT() asm volatile("cp.async.commit_group;" ::: "memory")
#define CP_WAIT1()  asm volatile("cp.async.wait_group 1;" ::: "memory")
#define CP_WAIT0()  asm volatile("cp.async.wait_group 0;" ::: "memory")
#define LDSM4(R, addr) \
    asm volatile("ldmatrix.sync.aligned.m8n8.x4.shared.b16 {%0,%1,%2,%3}, [%4];" \
        : "=r"((R)[0]), "=r"((R)[1]), "=r"((R)[2]), "=r"((R)[3]) : "r"(addr))

__device__ __forceinline__ void mmaop(float* c, const uint32_t* a, const uint32_t* b) {
    asm volatile("mma.sync.aligned.m16n8k16.row.col.f32.bf16.bf16.f32 "
        "{%0,%1,%2,%3}, {%4,%5,%6,%7}, {%8,%9}, {%0,%1,%2,%3};"
        : "+f"(c[0]), "+f"(c[1]), "+f"(c[2]), "+f"(c[3])
        : "r"(a[0]), "r"(a[1]), "r"(a[2]), "r"(a[3]), "r"(b[0]), "r"(b[1]));
}
__device__ __forceinline__ void mmaop_h(float* c, const uint32_t* a, const uint32_t* b) {
    asm volatile("mma.sync.aligned.m16n8k16.row.col.f32.f16.f16.f32 "
        "{%0,%1,%2,%3}, {%4,%5,%6,%7}, {%8,%9}, {%0,%1,%2,%3};"
        : "+f"(c[0]), "+f"(c[1]), "+f"(c[2]), "+f"(c[3])
        : "r"(a[0]), "r"(a[1]), "r"(a[2]), "r"(a[3]), "r"(b[0]), "r"(b[1]));
}
__device__ __forceinline__ float sigmoidf_(float x) { return 1.0f / (1.0f + expf(-x)); }
__device__ __forceinline__ void sp2(bf16* H, bf16* L, int i, float a, float b) {
    bf16 ha = __float2bfloat16(a), hb = __float2bfloat16(b);
    bf162 hv; hv.x = ha; hv.y = hb;
    bf162 lv; lv.x = __float2bfloat16(a - __bfloat162float(ha));
    lv.y = __float2bfloat16(b - __bfloat162float(hb));
    *(bf162*)&H[i] = hv; *(bf162*)&L[i] = lv;
}
__device__ __forceinline__ void sp2h(__half* H, __half* L, int i, float a, float b) {
    __half ha = __float2half_rn(a), hb = __float2half_rn(b);
    __half2 hv; hv.x = ha; hv.y = hb;
    __half2 lv; lv.x = __float2half_rn(a - __half2float(ha));
    lv.y = __float2half_rn(b - __half2float(hb));
    *(__half2*)&H[i] = hv; *(__half2*)&L[i] = lv;
}

// ---- generic split-3 bf16 mma GEMM: D[TM x TN] = A[TM,K] @ B[N,K]^T ----
#define ROWB 80
template<int TM, int TN, typename Epi>
__device__ __forceinline__ void mma_gemm(
    const bf16* __restrict__ Ah, const bf16* __restrict__ Al, int lda, int m0,
    const bf16* __restrict__ Bh, const bf16* __restrict__ Bl, int ldb, int n0,
    int K, Epi epi)
{
    extern __shared__ char smem[];
    constexpr int ASZ = TM * ROWB, BSZ = TN * ROWB, STG = 2*ASZ + 2*BSZ;
    constexpr int WM = TM / 4, WN = TN / 2, FM = WM / 16, NF = WN / 8;
    constexpr int GG = (NF > 4) ? 4 : NF;
    const uint32_t s0 = smem_u32(smem);
    const int tid = threadIdx.x, lane = tid & 31, wid = tid >> 5;
    const int wm = wid >> 1, wn = wid & 1;
    const int lrow = lane & 15, lhalf = lane >> 4;
    float acc[FM][NF][4] = {};

    auto issue = [&](int ch, int st) {
        uint32_t d = s0 + st * STG;
        int k0 = ch * 32;
        #pragma unroll
        for (int v = tid; v < TM * 4; v += 256) {
            int row = v >> 2, c = v & 3;
            cpasync16(d + row*ROWB + c*16,       Ah + (m0+row)*lda + k0 + c*8);
            cpasync16(d + ASZ + row*ROWB + c*16, Al + (m0+row)*lda + k0 + c*8);
        }
        #pragma unroll
        for (int v = tid; v < TN * 4; v += 256) {
            int row = v >> 2, c = v & 3;
            cpasync16(d + 2*ASZ + row*ROWB + c*16,       Bh + (n0+row)*ldb + k0 + c*8);
            cpasync16(d + 2*ASZ + BSZ + row*ROWB + c*16, Bl + (n0+row)*ldb + k0 + c*8);
        }
        CP_COMMIT();
    };

    const int NC = K / 32;
    issue(0, 0);
    for (int ch = 0; ch < NC; ch++) {
        int st = ch & 1;
        if (ch + 1 < NC) { issue(ch + 1, (ch + 1) & 1); CP_WAIT1(); }
        else CP_WAIT0();
        __syncthreads();
        uint32_t d = s0 + st * STG;
        #pragma unroll
        for (int kk = 0; kk < 2; kk++) {
            uint32_t ah[FM][4], al[FM][4];
            #pragma unroll
            for (int f = 0; f < FM; f++) {
                uint32_t a = d + (wm*WM + f*16 + lrow)*ROWB + lhalf*16 + kk*32;
                LDSM4(ah[f], a);
                LDSM4(al[f], a + ASZ);
            }
            #pragma unroll
            for (int gg = 0; gg < NF; gg += GG) {
                uint32_t bh[GG][2], bl[GG][2];
                #pragma unroll
                for (int g2 = 0; g2 < GG; g2 += 2) {
                    int g = gg + g2;
                    uint32_t b = d + 2*ASZ + (wn*WN + g*8 + lrow)*ROWB + lhalf*16 + kk*32;
                    uint32_t t4[4];
                    LDSM4(t4, b);
                    bh[g2][0]=t4[0]; bh[g2][1]=t4[2]; bh[g2+1][0]=t4[1]; bh[g2+1][1]=t4[3];
                    LDSM4(t4, b + BSZ);
                    bl[g2][0]=t4[0]; bl[g2][1]=t4[2]; bl[g2+1][0]=t4[1]; bl[g2+1][1]=t4[3];
                }
                #pragma unroll
                for (int f = 0; f < FM; f++)
                    #pragma unroll
                    for (int g2 = 0; g2 < GG; g2++) {
                        mmaop(acc[f][gg+g2], ah[f], bh[g2]);
                        mmaop(acc[f][gg+g2], ah[f], bl[g2]);
                        mmaop(acc[f][gg+g2], al[f], bh[g2]);
                    }
            }
        }
        __syncthreads();
    }
    #pragma unroll
    for (int f = 0; f < FM; f++)
        #pragma unroll
        for (int g = 0; g < NF; g++) {
            int r = m0 + wm*WM + f*16 + (lane >> 2);
            int c = n0 + wn*WN + g*8 + (lane & 3)*2;
            epi(r,     c, acc[f][g][0], acc[f][g][1]);
            epi(r + 8, c, acc[f][g][2], acc[f][g][3]);
        }
}

// ---- 2-term fp16 GEMM: D = (Ah+Al)[TM,K] @ Bh[N,K]^T  (A hi/lo fp16, B fp16) ----
template<int TM, int TN, typename Epi>
__device__ __forceinline__ void mma_gemm_h2(
    const __half* __restrict__ Ah, const __half* __restrict__ Al, int lda, int m0,
    const __half* __restrict__ Bh, int ldb, int n0, int K, Epi epi)
{
    extern __shared__ char smem[];
    constexpr int ASZ = TM * ROWB, BSZ = TN * ROWB, STG = 2*ASZ + BSZ;
    constexpr int WM = TM / 4, WN = TN / 2, FM = WM / 16, NF = WN / 8;
    constexpr int GG = (NF > 4) ? 4 : NF;
    const uint32_t s0 = smem_u32(smem);
    const int tid = threadIdx.x, lane = tid & 31, wid = tid >> 5;
    const int wm = wid >> 1, wn = wid & 1;
    const int lrow = lane & 15, lhalf = lane >> 4;
    float acc[FM][NF][4] = {};

    auto issue = [&](int ch, int st) {
        uint32_t d = s0 + st * STG;
        int k0 = ch * 32;
        #pragma unroll
        for (int v = tid; v < TM * 4; v += 256) {
            int row = v >> 2, c = v & 3;
            cpasync16(d + row*ROWB + c*16,       Ah + (m0+row)*lda + k0 + c*8);
            cpasync16(d + ASZ + row*ROWB + c*16, Al + (m0+row)*lda + k0 + c*8);
        }
        #pragma unroll
        for (int v = tid; v < TN * 4; v += 256) {
            int row = v >> 2, c = v & 3;
            cpasync16(d + 2*ASZ + row*ROWB + c*16, Bh + (n0+row)*ldb + k0 + c*8);
        }
        CP_COMMIT();
    };

    const int NC = K / 32;
    issue(0, 0);
    for (int ch = 0; ch < NC; ch++) {
        int st = ch & 1;
        if (ch + 1 < NC) { issue(ch + 1, (ch + 1) & 1); CP_WAIT1(); }
        else CP_WAIT0();
        __syncthreads();
        uint32_t d = s0 + st * STG;
        #pragma unroll
        for (int kk = 0; kk < 2; kk++) {
            uint32_t ah[FM][4], al[FM][4];
            #pragma unroll
            for (int f = 0; f < FM; f++) {
                uint32_t a = d + (wm*WM + f*16 + lrow)*ROWB + lhalf*16 + kk*32;
                LDSM4(ah[f], a);
                LDSM4(al[f], a + ASZ);
            }
            #pragma unroll
            for (int gg = 0; gg < NF; gg += GG) {
                uint32_t bh[GG][2];
                #pragma unroll
                for (int g2 = 0; g2 < GG; g2 += 2) {
                    int g = gg + g2;
                    uint32_t b = d + 2*ASZ + (wn*WN + g*8 + lrow)*ROWB + lhalf*16 + kk*32;
                    uint32_t t4[4];
                    LDSM4(t4, b);
                    bh[g2][0]=t4[0]; bh[g2][1]=t4[2]; bh[g2+1][0]=t4[1]; bh[g2+1][1]=t4[3];
                }
                #pragma unroll
                for (int f = 0; f < FM; f++)
                    #pragma unroll
                    for (int g2 = 0; g2 < GG; g2++) {
                        mmaop_h(acc[f][gg+g2], ah[f], bh[g2]);
                        mmaop_h(acc[f][gg+g2], al[f], bh[g2]);
                    }
            }
        }
        __syncthreads();
    }
    #pragma unroll
    for (int f = 0; f < FM; f++)
        #pragma unroll
        for (int g = 0; g < NF; g++) {
            int r = m0 + wm*WM + f*16 + (lane >> 2);
            int c = n0 + wn*WN + g*8 + (lane & 3)*2;
            epi(r,     c, acc[f][g][0], acc[f][g][1]);
            epi(r + 8, c, acc[f][g][2], acc[f][g][3]);
        }
}
#define SMEM_S  (2 * (2*64*ROWB + 2*32*ROWB))      // 30720
#define SMEM_X  (2 * (2*128*ROWB + 2*128*ROWB))    // 81920
#define SMEM_H  (2 * (2*128*ROWB + 128*ROWB))      // 61440

// ---- prepack ----
__device__ __forceinline__ void pk_T_body(const float* __restrict__ src,
                                          bf16* __restrict__ dh, bf16* __restrict__ dl,
                                          int K, int N, int Npad, int kb, int nb)
{
    __shared__ float tile[32][33];
    int tx = threadIdx.x & 31, ty = threadIdx.x >> 5;
    for (int i = ty; i < 32; i += 8) {
        int n = nb + tx;
        tile[i][tx] = (n < N) ? src[(kb + i) * N + n] : 0.f;
    }
    __syncthreads();
    for (int i = ty; i < 32; i += 8) {
        int n = nb + i, k = kb + tx;
        if (n < Npad) {
            float x = tile[tx][i];
            bf16 h = __float2bfloat16(x);
            dh[n * K + k] = h;
            dl[n * K + k] = __float2bfloat16(x - __bfloat162float(h));
        }
    }
}
__global__ __launch_bounds__(256) void pk_T(const float* __restrict__ src,
                                            bf16* __restrict__ dh, bf16* __restrict__ dl,
                                            int K, int N, int Npad)
{
    pk_T_body(src, dh, dl, K, N, Npad, blockIdx.y * 32, blockIdx.x * 32);
}
__global__ __launch_bounds__(256) void pk_gru(const float* __restrict__ Wu,
                                              const float* __restrict__ Wr,
                                              const float* __restrict__ Wc,
                                              bf16* __restrict__ Wgh,
                                              bf16* __restrict__ Wgl)
{
    int z = blockIdx.z;
    int gate = (z < 3) ? z : z - 3, layer = z / 3;
    const float* src = ((gate == 0) ? Wu : (gate == 1) ? Wr : Wc) + layer * 1024 * Hh;
    pk_T_body(src, Wgh + z*SZGRU, Wgl + z*SZGRU, 1024, Hh, Hh,
              blockIdx.y * 32, blockIdx.x * 32);
}
__global__ __launch_bounds__(256) void pk_Wo(const float* __restrict__ src)
{
    __shared__ float tile[32][33];
    int kb = blockIdx.y * 32, nb = blockIdx.x * 32;
    int tx = threadIdx.x & 31, ty = threadIdx.x >> 5;
    for (int i = ty; i < 32; i += 8) {
        int n = nb + tx;
        tile[i][tx] = (n < Vv) ? src[(kb + i) * Vv + n] : 0.f;
    }
    __syncthreads();
    for (int i = ty; i < 32; i += 8) {
        int n = nb + i, k = kb + tx;
        g_WoH[n * Hh + k] = __float2half_rn(tile[tx][i]);
    }
}
__global__ __launch_bounds__(256) void pk_vgg(const float* __restrict__ src)
{
    int i = (blockIdx.x * 256 + threadIdx.x) * 2;
    sp2(g_vgg_h, g_vgg_l, i, src[i], src[i + 1]);
}
__global__ __launch_bounds__(256) void k_gather(const float* __restrict__ emb,
                                                const int* __restrict__ tok)
{
    int idx = (blockIdx.x * 256 + threadIdx.x) * 2;
    int r = idx >> 9, e = idx & 511;
    int token = tok[(r & 127) * Tt + (r >> 7)];
    sp2(g_xemb_h, g_xemb_l, idx, emb[token * Hh + e], emb[token * Hh + e + 1]);
}

// ---- init: split-K partials then finalize ----
__global__ __launch_bounds__(256, 1) void k_initp()
{
    int cta = blockIdx.x;
    int ks = cta >> 5, mt = (cta >> 4) & 1, nt = cta & 15;
    int koff = ks * 1024;
    float* out = g_ipart[ks];
    mma_gemm<64,32>(g_vgg_h + koff, g_vgg_l + koff, Ff, mt*64,
                    g_Win_h + koff, g_Win_l + koff, Ff, nt*32, 1024,
        [&](int r, int c, float v0, float v1) {
            out[r*Hh + c] = v0; out[r*Hh + c + 1] = v1;
        });
}
__global__ __launch_bounds__(256) void k_initf(const float* __restrict__ b_in)
{
    int i = blockIdx.x * 256 + threadIdx.x;
    float v = tanhf(g_ipart[0][i] + g_ipart[1][i] + g_ipart[2][i] + g_ipart[3][i]
                    + b_in[i & 511]);
    g_h0f[i] = v; g_h1f[i] = v;
    bf16 h = __float2bfloat16(v);
    bf16 l = __float2bfloat16(v - __bfloat162float(h));
    g_h0h[i] = h; g_h0l[i] = l;
    int ci = (i >> 9) * 1024 + 512 + (i & 511);
    g_c1h[ci] = h; g_c1l[ci] = l;
}

// ---- layer0 x-projections for all t (128x128 tiles) ----
__global__ __launch_bounds__(256, 2) void k_xpre(const float* __restrict__ bu,
                                                 const float* __restrict__ br,
                                                 const float* __restrict__ bc)
{
    int n0 = blockIdx.x * 128, m0 = blockIdx.y * 128, gate = blockIdx.z;
    const float* bi = (gate == 0) ? bu : (gate == 1) ? br : bc;
    float* out = (gate == 0) ? g_Xu0 : (gate == 1) ? g_Xr0 : g_Xc0;
    mma_gemm<128,128>(g_xemb_h, g_xemb_l, Hh, m0,
                      g_Wgru_h + gate*SZGRU, g_Wgru_l + gate*SZGRU, 1024, n0, Hh,
        [&](int r, int c, float v0, float v1) {
            float2 val = make_float2(v0 + bi[c], v1 + bi[c + 1]);
            *(float2*)&out[r*Hh + c] = val;
        });
}

// ---- wave UR ----
__global__ __launch_bounds__(256, 1) void k_ur(int w,
                                               const float* __restrict__ bu1,
                                               const float* __restrict__ br1)
{
    int nt = blockIdx.x, mt = blockIdx.y, z = blockIdx.z;
    int n0 = nt * 32;
    if (z < 2) {
        if (w >= Tt) return;
        int gate = z;
        const float* X = (gate ? g_Xr0 : g_Xu0) + w * BH;
        mma_gemm<64,32>(g_h0h, g_h0l, Hh, mt*64,
            g_Wgru_h + gate*SZGRU + 512, g_Wgru_l + gate*SZGRU + 512,
            1024, n0, Hh,
            [&](int r, int c, float v0, float v1) {
                int idx = r*Hh + c;
                float s0 = sigmoidf_(v0 + X[idx]);
                float s1 = sigmoidf_(v1 + X[idx+1]);
                if (gate == 0) { g_u0f[idx] = s0; g_u0f[idx+1] = s1; }
                else sp2(g_rh0h, g_rh0l, idx, s0*g_h0f[idx], s1*g_h0f[idx+1]);
            });
    } else {
        if (w == 0) return;
        int gate = z - 2, par = (w - 1) & 1;
        const float* bi = gate ? br1 : bu1;
        mma_gemm<64,32>(g_c1h, g_c1l, 1024, mt*64,
            g_Wgru_h + (3+gate)*SZGRU, g_Wgru_l + (3+gate)*SZGRU,
            1024, n0, 1024,
            [&](int r, int c, float v0, float v1) {
                int idx = r*Hh + c;
                float s0 = sigmoidf_(v0 + bi[c]);
                float s1 = sigmoidf_(v1 + bi[c+1]);
                if (gate == 0) { g_u1f[idx] = s0; g_u1f[idx+1] = s1; }
                else sp2(g_c2h[par], g_c2l[par], r*1024 + 512 + c,
                         s0*g_h1f[idx], s1*g_h1f[idx+1]);
            });
    }
}

// ---- wave C ----
__global__ __launch_bounds__(256, 1) void k_c(int w, const float* __restrict__ bc1)
{
    int nt = blockIdx.x, mt = blockIdx.y, z = blockIdx.z;
    int n0 = nt * 32;
    if (z == 0) {
        if (w >= Tt) return;
        int par = w & 1;
        const float* Xc = g_Xc0 + w * BH;
        mma_gemm<64,32>(g_rh0h, g_rh0l, Hh, mt*64,
            g_Wgru_h + 2*SZGRU + 512, g_Wgru_l + 2*SZGRU + 512,
            1024, n0, Hh,
            [&](int r, int c, float v0, float v1) {
                int idx = r*Hh + c;
                float c0 = tanhf(v0 + Xc[idx]), c1 = tanhf(v1 + Xc[idx+1]);
                float u0 = g_u0f[idx], u1 = g_u0f[idx+1];
                float h0 = u0*g_h0f[idx]   + (1.f-u0)*c0;
                float h1 = u1*g_h0f[idx+1] + (1.f-u1)*c1;
                g_h0f[idx] = h0; g_h0f[idx+1] = h1;
                sp2(g_h0h, g_h0l, idx, h0, h1);
                int ci = r*1024 + c;
                sp2(g_c1h, g_c1l, ci, h0, h1);
                sp2(g_c2h[par], g_c2l[par], ci, h0, h1);
            });
    } else {
        if (w == 0) return;
        int par = (w - 1) & 1;
        mma_gemm<64,32>(g_c2h[par], g_c2l[par], 1024, mt*64,
            g_Wgru_h + 5*SZGRU, g_Wgru_l + 5*SZGRU, 1024, n0, 1024,
            [&](int r, int c, float v0, float v1) {
                int idx = r*Hh + c;
                float c0 = tanhf(v0 + bc1[c]), c1 = tanhf(v1 + bc1[c+1]);
                float u0 = g_u1f[idx], u1 = g_u1f[idx+1];
                float h0 = u0*g_h1f[idx]   + (1.f-u0)*c0;
                float h1 = u1*g_h1f[idx+1] + (1.f-u1)*c1;
                g_h1f[idx] = h0; g_h1f[idx+1] = h1;
                sp2(g_c1h, g_c1l, r*1024 + 512 + c, h0, h1);
                sp2h(g_X1ah, g_X1al, ((w-1)*Bb + r)*Hh + c, h0, h1);
            });
    }
}

// ---- logits: 2-term fp16 ----
__global__ __launch_bounds__(256, 2) void k_logits(const float* __restrict__ bout,
                                                   float* __restrict__ out)
{
    int n0 = blockIdx.x * 128, m0 = blockIdx.y * 128;
    mma_gemm_h2<128,128>(g_X1ah, g_X1al, Hh, m0, g_WoH, Hh, n0, Hh,
        [&](int r, int c, float v0, float v1) {
            if (c < Vv) {
                int t = r >> 7, b = r & 127;
                long long base = (long long)(b * Tt + t) * Vv;
                out[base + c] = v0 + bout[c];
                if (c + 1 < Vv) out[base + c + 1] = v1 + bout[c + 1];
            }
        });
}

__global__ __launch_bounds__(256) void k_final(float* __restrict__ out)
{
    int i = blockIdx.x * 256 + threadIdx.x;
    out[(long long)Bb * Tt * Vv + i] = (i >> 16) ? g_h1f[i & (BH-1)] : g_h0f[i & (BH-1)];
}

// ---- launch ----
extern "C" void kernel_launch(void* const* d_in, const int* in_sizes, int n_in,
                              void* d_out, int out_size)
{
    const float* vgg   = (const float*)d_in[0];
    const int*   xTok  = (const int*)  d_in[1];
    const float* emb   = (const float*)d_in[2];
    const float* W_in  = (const float*)d_in[3];
    const float* b_in  = (const float*)d_in[4];
    const float* Wu    = (const float*)d_in[5];
    const float* bu    = (const float*)d_in[6];
    const float* Wr    = (const float*)d_in[7];
    const float* br    = (const float*)d_in[8];
    const float* Wc    = (const float*)d_in[9];
    const float* bc    = (const float*)d_in[10];
    const float* W_out = (const float*)d_in[11];
    const float* b_out = (const float*)d_in[12];
    float* out = (float*)d_out;

    cudaFuncSetAttribute(k_xpre,   cudaFuncAttributeMaxDynamicSharedMemorySize, SMEM_X);
    cudaFuncSetAttribute(k_logits, cudaFuncAttributeMaxDynamicSharedMemorySize, SMEM_H);

    bf16 *Wgh, *Wgl, *Wih, *Wil;
    cudaGetSymbolAddress((void**)&Wgh, g_Wgru_h);
    cudaGetSymbolAddress((void**)&Wgl, g_Wgru_l);
    cudaGetSymbolAddress((void**)&Wih, g_Win_h);
    cudaGetSymbolAddress((void**)&Wil, g_Win_l);

    pk_vgg<<<(Bb*Ff/2)/256, 256>>>(vgg);
    pk_T<<<dim3(16, 128), 256>>>(W_in, Wih, Wil, Ff, Hh, Hh);
    pk_gru<<<dim3(16, 32, 6), 256>>>(Wu, Wr, Wc, Wgh, Wgl);
    pk_Wo<<<dim3(Vpad/32, 16), 256>>>(W_out);

    k_initp<<<128, 256, SMEM_S>>>();
    k_initf<<<BH/256, 256>>>(b_in);
    k_gather<<<(TBH/2)/256, 256>>>(emb, xTok);
    k_xpre<<<dim3(4, Tt*Bb/128, 3), 256, SMEM_X>>>(bu, br, bc);

    for (int w = 0; w <= Tt; w++) {
        k_ur<<<dim3(16, 2, 4), 256, SMEM_S>>>(w, bu + Hh, br + Hh);
        k_c <<<dim3(16, 2, 2), 256, SMEM_S>>>(w, bc + Hh);
    }

    k_logits<<<dim3(Vpad/128, Tt*Bb/128), 256, SMEM_H>>>(b_out, out);
    k_final<<<(2*BH)/256, 256>>>(out);
}